// round 13
// baseline (speedup 1.0000x reference)
#include <cuda_runtime.h>
#include <cuda_bf16.h>
#include <math.h>
#include <stdint.h>

// Problem constants
#define B_   2
#define S_   2048
#define D_   2048
#define H_   16
#define HD_  128
#define M_   (B_ * S_)      // 4096
#define NQKV (3 * D_)       // 6144
#define K_   D_             // 2048

// ---------------- scratch (device globals) ---------------------------------
__device__ float g_qkv[(size_t)M_ * NQKV];
__device__ float g_q  [(size_t)M_ * D_];   // [b,h,s,hd], tf32-rounded
__device__ float g_k  [(size_t)M_ * D_];
__device__ float g_v  [(size_t)M_ * D_];
__device__ float g_attn[(size_t)M_ * D_];  // [b,s,h,hd], tf32-rounded
__device__ float g_wor [(size_t)D_ * D_];  // w_out  tf32-rounded
__device__ float g_xr  [(size_t)M_ * D_];  // x      tf32-rounded
__device__ float g_wqr [(size_t)NQKV * D_];// w_qkv  tf32-rounded

// ======================= PTX helpers (compute_103-safe) =====================
__device__ __forceinline__ uint32_t s2u(const void* p) {
    uint32_t a;
    asm("{ .reg .u64 t; cvta.to.shared.u64 t, %1; cvt.u32.u64 %0, t; }"
        : "=r"(a) : "l"(p));
    return a;
}
__device__ __forceinline__ void cp16(uint32_t dst, const void* src) {
    asm volatile("cp.async.ca.shared.global [%0], [%1], 16;" :: "r"(dst), "l"(src));
}
__device__ __forceinline__ void cp_commit() {
    asm volatile("cp.async.commit_group;" ::: "memory");
}
__device__ __forceinline__ void cp_wait0() {
    asm volatile("cp.async.wait_group 0;" ::: "memory");
}
__device__ __forceinline__ void cp_wait1() {
    asm volatile("cp.async.wait_group 1;" ::: "memory");
}
__device__ __forceinline__ void ldsm_x4(uint32_t* r, uint32_t addr) {
    asm volatile("ldmatrix.sync.aligned.m8n8.x4.shared.b16 {%0,%1,%2,%3}, [%4];"
                 : "=r"(r[0]), "=r"(r[1]), "=r"(r[2]), "=r"(r[3]) : "r"(addr));
}
__device__ __forceinline__ void mma_tf32(float* d, const uint32_t* a, const uint32_t* b) {
    asm volatile(
        "mma.sync.aligned.m16n8k8.row.col.f32.tf32.tf32.f32 "
        "{%0,%1,%2,%3}, {%4,%5,%6,%7}, {%8,%9}, {%0,%1,%2,%3};"
        : "+f"(d[0]), "+f"(d[1]), "+f"(d[2]), "+f"(d[3])
        : "r"(a[0]), "r"(a[1]), "r"(a[2]), "r"(a[3]), "r"(b[0]), "r"(b[1]));
}
__device__ __forceinline__ float tf32r(float x) {
    uint32_t u;
    asm("cvt.rna.tf32.f32 %0, %1;" : "=r"(u) : "f"(x));
    return __uint_as_float(u);
}

// ======================= fp32 -> tf32(rna) round ===========================
__global__ __launch_bounds__(256)
void round_tf32(const float4* __restrict__ in, float4* __restrict__ out, int n4)
{
    int i = blockIdx.x * 256 + threadIdx.x;
    if (i >= n4) return;
    float4 v = in[i];
    float4 r = {tf32r(v.x), tf32r(v.y), tf32r(v.z), tf32r(v.w)};
    out[i] = r;
}

// ======================= single-pass tf32 GEMM =============================
// C[M,N] = A[M,K] * B[N,K]^T, A/B fp32 already tf32-rounded (RNA).
// 128x128 CTA tile, 4 warps of 64x64, BK=32, 3-stage cp.async ring,
// swizzled fp32 smem, ldmatrix fragments. 2 CTAs/SM (192KB smem).
#define T_STAGE_BYTES 32768
#define T_SMEM_BYTES  (3 * T_STAGE_BYTES)   // 98304

__device__ __forceinline__ void t_load_stage(uint32_t sbase, const float* gA,
                                             const float* gB, int k0, int t)
{
    const float* gs[2] = {gA, gB};
#pragma unroll
    for (int ts = 0; ts < 2; ++ts) {
        const float* g = gs[ts] + k0;
        uint32_t tb = sbase + ts * 16384;
#pragma unroll
        for (int i = 0; i < 8; ++i) {
            int c = t + i * 128;              // 0..1023 (128 threads)
            int row = c >> 3, cc = c & 7;
            uint32_t off = row * 128 + cc * 16;
            uint32_t sw = off ^ ((off >> 3) & 0x70);
            cp16(tb + sw, g + (size_t)row * K_ + cc * 4);
        }
    }
    cp_commit();
}

__global__ __launch_bounds__(128, 2)
void gemm_tf32(const float* __restrict__ A, const float* __restrict__ B,
               float* __restrict__ C, int N)
{
    extern __shared__ __align__(1024) float smf[];
    const int t    = threadIdx.x;
    const int wid  = t >> 5;                 // 0..3
    const int lane = t & 31;
    const int g    = lane >> 2;
    const int c    = lane & 3;
    const int m0w  = (wid >> 1) * 64;        // 0 / 64
    const int n0w  = (wid & 1) * 64;         // 0 / 64
    const int rowBase = blockIdx.y << 7;
    const int colBase = blockIdx.x << 7;

    uint32_t sb = s2u(smf);

    // ldmatrix lane geometry (fp32 quadrants, 16B rows)
    const int a_row = (lane & 7) + ((lane >> 3) & 1) * 8;   // A: row within m16
    const int a_cb  = (lane >> 4) * 16;                     // A: k-half byte offset
    const int b_row = (lane & 7) + ((lane >> 4) & 1) * 8;   // B: row within nb-pair
    const int b_cb  = ((lane >> 3) & 1) * 16;               // B: k-half byte offset
    const uint32_t xort = (uint32_t)(lane & 7) << 4;        // swizzle XOR

    uint32_t abase[4], bbase[4];
#pragma unroll
    for (int mb = 0; mb < 4; ++mb)
        abase[mb] = (uint32_t)(m0w + mb * 16 + a_row) * 128 + a_cb;
#pragma unroll
    for (int nbp = 0; nbp < 4; ++nbp)
        bbase[nbp] = (uint32_t)(n0w + nbp * 16 + b_row) * 128 + b_cb;

    float acc[4][8][4];
#pragma unroll
    for (int mb = 0; mb < 4; ++mb)
#pragma unroll
        for (int nb = 0; nb < 8; ++nb)
#pragma unroll
            for (int r = 0; r < 4; ++r) acc[mb][nb][r] = 0.f;

    const float* gA = A + (size_t)rowBase * K_;
    const float* gB = B + (size_t)colBase * K_;

    const int NT = K_ / 32;   // 64

    // preload stages 0, 1
    t_load_stage(sb,                 gA, gB, 0,  t);
    t_load_stage(sb + T_STAGE_BYTES, gA, gB, 32, t);

    int sidx = 0;   // stage of current kt
    for (int kt = 0; kt < NT; ++kt) {
        if (kt + 1 < NT) cp_wait1(); else cp_wait0();  // stage kt complete
        __syncthreads();
        if (kt + 2 < NT) {
            int sld = sidx + 2; if (sld >= 3) sld -= 3;
            t_load_stage(sb + sld * T_STAGE_BYTES, gA, gB, (kt + 2) << 5, t);
        }
        const uint32_t stA = sb + sidx * T_STAGE_BYTES;
        const uint32_t stB = stA + 16384;

#pragma unroll
        for (int ks = 0; ks < 4; ++ks) {
            const uint32_t ko = (uint32_t)ks * 32;
            uint32_t a[4][4], bfr[8][2];
#pragma unroll
            for (int mb = 0; mb < 4; ++mb)
                ldsm_x4(a[mb], stA + ((abase[mb] + ko) ^ xort));
#pragma unroll
            for (int nbp = 0; nbp < 4; ++nbp) {
                uint32_t r[4];
                ldsm_x4(r, stB + ((bbase[nbp] + ko) ^ xort));
                bfr[2 * nbp][0]     = r[0];
                bfr[2 * nbp][1]     = r[1];
                bfr[2 * nbp + 1][0] = r[2];
                bfr[2 * nbp + 1][1] = r[3];
            }
#pragma unroll
            for (int mb = 0; mb < 4; ++mb)
#pragma unroll
                for (int nb = 0; nb < 8; ++nb)
                    mma_tf32(acc[mb][nb], a[mb], bfr[nb]);
        }
        ++sidx; if (sidx == 3) sidx = 0;
    }

#pragma unroll
    for (int mb = 0; mb < 4; ++mb)
#pragma unroll
        for (int nb = 0; nb < 8; ++nb) {
            int row = rowBase + m0w + mb * 16 + g;
            int col = colBase + n0w + nb * 8 + 2 * c;
            float2 v0 = {acc[mb][nb][0], acc[mb][nb][1]};
            float2 v1 = {acc[mb][nb][2], acc[mb][nb][3]};
            *(float2*)(C + (size_t)row * N + col)       = v0;
            *(float2*)(C + (size_t)(row + 8) * N + col) = v1;
        }
}

// ---------------------------------------------------------------------------
// RoPE + unit-norm + q*attn_scale; tf32-rounded q/k/v in [b,h,s,hd].
// ---------------------------------------------------------------------------
__global__ __launch_bounds__(64)
void rope_norm_kernel(const float* __restrict__ qkv,
                      const float* __restrict__ freqs,
                      const float* __restrict__ scale_p,
                      float* __restrict__ gq, float* __restrict__ gk,
                      float* __restrict__ gv)
{
    const int idx = blockIdx.x;
    const int h = idx % H_;
    const int s = (idx / H_) % S_;
    const int b = idx / (H_ * S_);
    const int i = threadIdx.x;

    const float* base = qkv + (size_t)(b * S_ + s) * NQKV + h * HD_;
    float q0 = base[2 * i],           q1 = base[2 * i + 1];
    float k0 = base[D_ + 2 * i],      k1 = base[D_ + 2 * i + 1];
    float v0 = base[2 * D_ + 2 * i],  v1 = base[2 * D_ + 2 * i + 1];

    float cs = freqs[((size_t)s * 64 + i) * 2 + 0];
    float sn = freqs[((size_t)s * 64 + i) * 2 + 1];

    float qr = q0 * cs - q1 * sn, qi = q0 * sn + q1 * cs;
    float kr = k0 * cs - k1 * sn, ki = k0 * sn + k1 * cs;

    float sq = qr * qr + qi * qi;
    float sk = kr * kr + ki * ki;
#pragma unroll
    for (int off = 16; off > 0; off >>= 1) {
        sq += __shfl_xor_sync(0xffffffffu, sq, off);
        sk += __shfl_xor_sync(0xffffffffu, sk, off);
    }
    __shared__ float smq[2], smk[2];
    if ((i & 31) == 0) { smq[i >> 5] = sq; smk[i >> 5] = sk; }
    __syncthreads();
    float nq = sqrtf(smq[0] + smq[1]) + 1e-6f;
    float nk = sqrtf(smk[0] + smk[1]) + 1e-6f;

    float scl = *scale_p;
    float qs = scl / nq;
    float ks = 1.0f / nk;

    size_t o = ((size_t)(b * H_ + h) * S_ + s) * HD_;
    gq[o + 2 * i] = tf32r(qr * qs);  gq[o + 2 * i + 1] = tf32r(qi * qs);
    gk[o + 2 * i] = tf32r(kr * ks);  gk[o + 2 * i + 1] = tf32r(ki * ks);
    gv[o + 2 * i] = tf32r(v0);       gv[o + 2 * i + 1] = tf32r(v1);
}

// ---------------------------------------------------------------------------
// tf32 flash attention (R8, unchanged). BM=128, BN=64, 256 threads.
// ---------------------------------------------------------------------------
#define QS_OFF 0
#define KS_OFF (128 * 132)
#define KS_BUF (64 * 132)
#define VS_OFF (KS_OFF + 2 * KS_BUF)
#define PS_OFF (VS_OFF + 64 * 136)
#define AT_SMEM_FLOATS (PS_OFF + 128 * 68)
#define AT_SMEM_BYTES (AT_SMEM_FLOATS * 4)    // 204800

__global__ __launch_bounds__(256)
void flash_tc(const float* __restrict__ gq, const float* __restrict__ gk,
              const float* __restrict__ gv, float* __restrict__ gout)
{
    extern __shared__ float sm[];
    uint32_t smb = s2u(sm);
    const int t    = threadIdx.x;
    const int w    = t >> 5;
    const int lane = t & 31;
    const int g    = lane >> 2;
    const int c    = lane & 3;
    const int qt   = (gridDim.x - 1) - blockIdx.x;   // heavy tiles first
    const int bh   = blockIdx.y;
    const int b    = bh >> 4;
    const int h    = bh & 15;
    const int qr0  = w * 16;

    const float* Qg = gq + ((size_t)bh * S_ + qt * 128) * HD_;
    const float* Kg = gk + (size_t)bh * S_ * HD_;
    const float* Vg = gv + (size_t)bh * S_ * HD_;

#pragma unroll
    for (int i = 0; i < 16; ++i) {
        int ci = t + i * 256;
        int row = ci >> 5, cc = ci & 31;
        cp16(smb + (QS_OFF + row * 132 + cc * 4) * 4, Qg + row * HD_ + cc * 4);
    }
    cp_commit();

    const int nkv = 2 * qt + 2;

#pragma unroll
    for (int i = 0; i < 8; ++i) {
        int ci = t + i * 256;
        int row = ci >> 5, cc = ci & 31;
        cp16(smb + (KS_OFF + row * 132 + cc * 4) * 4, Kg + (size_t)row * HD_ + cc * 4);
    }
    cp_commit();
#pragma unroll
    for (int i = 0; i < 8; ++i) {
        int ci = t + i * 256;
        int row = ci >> 5, cc = ci & 31;
        cp16(smb + (VS_OFF + row * 136 + cc * 4) * 4, Vg + (size_t)row * HD_ + cc * 4);
    }
    cp_commit();

    float O[16][4];
#pragma unroll
    for (int nb = 0; nb < 16; ++nb)
#pragma unroll
        for (int r = 0; r < 4; ++r) O[nb][r] = 0.f;
    float m0 = -1e30f, m1 = -1e30f, l0 = 0.f, l1 = 0.f;

    for (int kt = 0; kt < nkv; ++kt) {
        cp_wait1();
        __syncthreads();

        if (kt + 1 < nkv) {
            const float* ksrc = Kg + (size_t)(kt + 1) * 64 * HD_;
            uint32_t kdst = smb + (KS_OFF + ((kt + 1) & 1) * KS_BUF) * 4;
#pragma unroll
            for (int i = 0; i < 8; ++i) {
                int ci = t + i * 256;
                int row = ci >> 5, cc = ci & 31;
                cp16(kdst + (row * 132 + cc * 4) * 4, ksrc + (size_t)row * HD_ + cc * 4);
            }
            cp_commit();
        }

        const int kbase = KS_OFF + (kt & 1) * KS_BUF;
        float sacc[8][4];
#pragma unroll
        for (int nb = 0; nb < 8; ++nb)
#pragma unroll
            for (int r = 0; r < 4; ++r) sacc[nb][r] = 0.f;

#pragma unroll
        for (int ks = 0; ks < 16; ++ks) {
            const int k0 = ks * 8;
            uint32_t a[4];
            a[0] = __float_as_uint(sm[QS_OFF + (qr0 + g) * 132 + k0 + c]);
            a[1] = __float_as_uint(sm[QS_OFF + (qr0 + g + 8) * 132 + k0 + c]);
            a[2] = __float_as_uint(sm[QS_OFF + (qr0 + g) * 132 + k0 + c + 4]);
            a[3] = __float_as_uint(sm[QS_OFF + (qr0 + g + 8) * 132 + k0 + c + 4]);
#pragma unroll
            for (int nb = 0; nb < 8; ++nb) {
                uint32_t bfr[2];
                bfr[0] = __float_as_uint(sm[kbase + (nb * 8 + g) * 132 + k0 + c]);
                bfr[1] = __float_as_uint(sm[kbase + (nb * 8 + g) * 132 + k0 + c + 4]);
                mma_tf32(sacc[nb], a, bfr);
            }
        }

        if (kt >= 2 * qt) {
            int rg0 = qt * 128 + qr0 + g;
#pragma unroll
            for (int nb = 0; nb < 8; ++nb) {
                int col = kt * 64 + nb * 8 + 2 * c;
                if (col     > rg0)     sacc[nb][0] = -1e30f;
                if (col + 1 > rg0)     sacc[nb][1] = -1e30f;
                if (col     > rg0 + 8) sacc[nb][2] = -1e30f;
                if (col + 1 > rg0 + 8) sacc[nb][3] = -1e30f;
            }
        }

        float rm0 = -1e30f, rm1 = -1e30f;
#pragma unroll
        for (int nb = 0; nb < 8; ++nb) {
            rm0 = fmaxf(rm0, fmaxf(sacc[nb][0], sacc[nb][1]));
            rm1 = fmaxf(rm1, fmaxf(sacc[nb][2], sacc[nb][3]));
        }
        rm0 = fmaxf(rm0, __shfl_xor_sync(0xffffffffu, rm0, 1));
        rm0 = fmaxf(rm0, __shfl_xor_sync(0xffffffffu, rm0, 2));
        rm1 = fmaxf(rm1, __shfl_xor_sync(0xffffffffu, rm1, 1));
        rm1 = fmaxf(rm1, __shfl_xor_sync(0xffffffffu, rm1, 2));
        float mn0 = fmaxf(m0, rm0), mn1 = fmaxf(m1, rm1);
        float al0 = __expf(m0 - mn0), al1 = __expf(m1 - mn1);
        float rs0 = 0.f, rs1 = 0.f;
#pragma unroll
        for (int nb = 0; nb < 8; ++nb) {
            sacc[nb][0] = __expf(sacc[nb][0] - mn0);
            sacc[nb][1] = __expf(sacc[nb][1] - mn0);
            sacc[nb][2] = __expf(sacc[nb][2] - mn1);
            sacc[nb][3] = __expf(sacc[nb][3] - mn1);
            rs0 += sacc[nb][0] + sacc[nb][1];
            rs1 += sacc[nb][2] + sacc[nb][3];
        }
        rs0 += __shfl_xor_sync(0xffffffffu, rs0, 1);
        rs0 += __shfl_xor_sync(0xffffffffu, rs0, 2);
        rs1 += __shfl_xor_sync(0xffffffffu, rs1, 1);
        rs1 += __shfl_xor_sync(0xffffffffu, rs1, 2);
        l0 = l0 * al0 + rs0;  m0 = mn0;
        l1 = l1 * al1 + rs1;  m1 = mn1;
#pragma unroll
        for (int nb = 0; nb < 16; ++nb) {
            O[nb][0] *= al0; O[nb][1] *= al0;
            O[nb][2] *= al1; O[nb][3] *= al1;
        }

#pragma unroll
        for (int nb = 0; nb < 8; ++nb) {
            int colp = nb * 8 + 2 * c;
            sm[PS_OFF + (qr0 + g) * 68 + colp]         = tf32r(sacc[nb][0]);
            sm[PS_OFF + (qr0 + g) * 68 + colp + 1]     = tf32r(sacc[nb][1]);
            sm[PS_OFF + (qr0 + g + 8) * 68 + colp]     = tf32r(sacc[nb][2]);
            sm[PS_OFF + (qr0 + g + 8) * 68 + colp + 1] = tf32r(sacc[nb][3]);
        }
        __syncwarp();

        if (kt + 1 < nkv) cp_wait1(); else cp_wait0();
        __syncthreads();

#pragma unroll
        for (int ks = 0; ks < 8; ++ks) {
            const int k0 = ks * 8;
            uint32_t a[4];
            a[0] = __float_as_uint(sm[PS_OFF + (qr0 + g) * 68 + k0 + c]);
            a[1] = __float_as_uint(sm[PS_OFF + (qr0 + g + 8) * 68 + k0 + c]);
            a[2] = __float_as_uint(sm[PS_OFF + (qr0 + g) * 68 + k0 + c + 4]);
            a[3] = __float_as_uint(sm[PS_OFF + (qr0 + g + 8) * 68 + k0 + c + 4]);
#pragma unroll
            for (int nb = 0; nb < 16; ++nb) {
                uint32_t bfr[2];
                bfr[0] = __float_as_uint(sm[VS_OFF + (k0 + c) * 136 + nb * 8 + g]);
                bfr[1] = __float_as_uint(sm[VS_OFF + (k0 + c + 4) * 136 + nb * 8 + g]);
                mma_tf32(O[nb], a, bfr);
            }
        }
        __syncthreads();

        if (kt + 1 < nkv) {
            const float* vsrc = Vg + (size_t)(kt + 1) * 64 * HD_;
#pragma unroll
            for (int i = 0; i < 8; ++i) {
                int ci = t + i * 256;
                int row = ci >> 5, cc = ci & 31;
                cp16(smb + (VS_OFF + row * 136 + cc * 4) * 4,
                     vsrc + (size_t)row * HD_ + cc * 4);
            }
            cp_commit();
        }
    }

    float inv0 = 1.f / l0, inv1 = 1.f / l1;
    int r0 = qt * 128 + qr0 + g;
    int r1 = r0 + 8;
#pragma unroll
    for (int nb = 0; nb < 16; ++nb) {
        int d = nb * 8 + 2 * c;
        float2 v0 = {tf32r(O[nb][0] * inv0), tf32r(O[nb][1] * inv0)};
        float2 v1 = {tf32r(O[nb][2] * inv1), tf32r(O[nb][3] * inv1)};
        *(float2*)(gout + ((size_t)(b * S_ + r0) * H_ + h) * HD_ + d) = v0;
        *(float2*)(gout + ((size_t)(b * S_ + r1) * H_ + h) * HD_ + d) = v1;
    }
}

// ---------------------------------------------------------------------------
extern "C" void kernel_launch(void* const* d_in, const int* in_sizes, int n_in,
                              void* d_out, int out_size)
{
    const float* x      = (const float*)d_in[0];
    const float* freqs  = (const float*)d_in[1];
    const float* wqkv   = (const float*)d_in[2];
    const float* wout   = (const float*)d_in[3];
    const float* ascale = (const float*)d_in[4];
    float* out = (float*)d_out;

    float *qkv, *q, *k, *v, *attn, *wor, *xr, *wqr;
    cudaGetSymbolAddress((void**)&qkv,  g_qkv);
    cudaGetSymbolAddress((void**)&q,    g_q);
    cudaGetSymbolAddress((void**)&k,    g_k);
    cudaGetSymbolAddress((void**)&v,    g_v);
    cudaGetSymbolAddress((void**)&attn, g_attn);
    cudaGetSymbolAddress((void**)&wor,  g_wor);
    cudaGetSymbolAddress((void**)&xr,   g_xr);
    cudaGetSymbolAddress((void**)&wqr,  g_wqr);

    cudaFuncSetAttribute(gemm_tf32, cudaFuncAttributeMaxDynamicSharedMemorySize,
                         T_SMEM_BYTES);
    cudaFuncSetAttribute(flash_tc, cudaFuncAttributeMaxDynamicSharedMemorySize,
                         AT_SMEM_BYTES);

    // 0) tf32(RNA) pre-round all GEMM operands
    {
        int n4 = (M_ * D_) / 4;
        round_tf32<<<(n4 + 255) / 256, 256>>>((const float4*)x, (float4*)xr, n4);
    }
    {
        int n4 = (NQKV * D_) / 4;
        round_tf32<<<(n4 + 255) / 256, 256>>>((const float4*)wqkv, (float4*)wqr, n4);
    }
    {
        int n4 = (D_ * D_) / 4;
        round_tf32<<<(n4 + 255) / 256, 256>>>((const float4*)wout, (float4*)wor, n4);
    }

    // 1) qkv = x @ w_qkv^T  (tf32, 4 warps x 64x64, 3-stage ring)
    gemm_tf32<<<dim3(NQKV / 128, M_ / 128), 128, T_SMEM_BYTES>>>(xr, wqr, qkv, NQKV);

    // 2) RoPE + norm + scale (tf32-rounded outputs)
    rope_norm_kernel<<<B_ * S_ * H_, 64>>>(qkv, freqs, ascale, q, k, v);

    // 3) flash attention -> tf32-rounded attn [b,s,h,hd]
    flash_tc<<<dim3(S_ / 128, B_ * H_), 256, AT_SMEM_BYTES>>>(q, k, v, attn);

    // 4) out = attn @ w_out^T  (tf32, 4 warps x 64x64, 3-stage ring)
    gemm_tf32<<<dim3(D_ / 128, M_ / 128), 128, T_SMEM_BYTES>>>(attn, wor, out, D_);
}

// round 14
// speedup vs baseline: 1.4264x; 1.4264x over previous
#include <cuda_runtime.h>
#include <cuda_fp16.h>
#include <math.h>
#include <stdint.h>

// Problem constants
#define B_   2
#define S_   2048
#define D_   2048
#define H_   16
#define HD_  128
#define M_   (B_ * S_)      // 4096
#define NQKV (3 * D_)       // 6144
#define K_   D_             // 2048

// ---------------- scratch (device globals) ---------------------------------
__device__ float g_qkv[(size_t)M_ * NQKV];
__device__ float g_q  [(size_t)M_ * D_];   // [b,h,s,hd], tf32-rounded
__device__ float g_k  [(size_t)M_ * D_];
__device__ float g_v  [(size_t)M_ * D_];

__device__ __align__(1024) __half g_xh  [(size_t)M_ * D_];     // x fp16
__device__ __align__(1024) __half g_wqh [(size_t)NQKV * D_];   // w_qkv fp16
__device__ __align__(1024) __half g_woh [(size_t)D_ * D_];     // w_out fp16
__device__ __align__(1024) __half g_atth[(size_t)M_ * D_];     // attn fp16 [b,s,h,hd]

// ======================= PTX helpers (compute_103-safe) =====================
__device__ __forceinline__ uint32_t s2u(const void* p) {
    uint32_t a;
    asm("{ .reg .u64 t; cvta.to.shared.u64 t, %1; cvt.u32.u64 %0, t; }"
        : "=r"(a) : "l"(p));
    return a;
}
__device__ __forceinline__ void cp16(uint32_t dst, const void* src) {
    asm volatile("cp.async.ca.shared.global [%0], [%1], 16;" :: "r"(dst), "l"(src));
}
__device__ __forceinline__ void cp_commit() {
    asm volatile("cp.async.commit_group;" ::: "memory");
}
__device__ __forceinline__ void cp_wait0() {
    asm volatile("cp.async.wait_group 0;" ::: "memory");
}
__device__ __forceinline__ void cp_wait1() {
    asm volatile("cp.async.wait_group 1;" ::: "memory");
}
__device__ __forceinline__ void ldsm_x4(uint32_t* r, uint32_t addr) {
    asm volatile("ldmatrix.sync.aligned.m8n8.x4.shared.b16 {%0,%1,%2,%3}, [%4];"
                 : "=r"(r[0]), "=r"(r[1]), "=r"(r[2]), "=r"(r[3]) : "r"(addr));
}
__device__ __forceinline__ void mma_fp16(float* d, const uint32_t* a, const uint32_t* b) {
    asm volatile(
        "mma.sync.aligned.m16n8k16.row.col.f32.f16.f16.f32 "
        "{%0,%1,%2,%3}, {%4,%5,%6,%7}, {%8,%9}, {%0,%1,%2,%3};"
        : "+f"(d[0]), "+f"(d[1]), "+f"(d[2]), "+f"(d[3])
        : "r"(a[0]), "r"(a[1]), "r"(a[2]), "r"(a[3]), "r"(b[0]), "r"(b[1]));
}
__device__ __forceinline__ void mma_tf32(float* d, const uint32_t* a, const uint32_t* b) {
    asm volatile(
        "mma.sync.aligned.m16n8k8.row.col.f32.tf32.tf32.f32 "
        "{%0,%1,%2,%3}, {%4,%5,%6,%7}, {%8,%9}, {%0,%1,%2,%3};"
        : "+f"(d[0]), "+f"(d[1]), "+f"(d[2]), "+f"(d[3])
        : "r"(a[0]), "r"(a[1]), "r"(a[2]), "r"(a[3]), "r"(b[0]), "r"(b[1]));
}
__device__ __forceinline__ float tf32r(float x) {
    uint32_t u;
    asm("cvt.rna.tf32.f32 %0, %1;" : "=r"(u) : "f"(x));
    return __uint_as_float(u);
}

// ======================= fp32 -> fp16(rn) convert ==========================
__global__ __launch_bounds__(256)
void to_half(const float4* __restrict__ in, uint2* __restrict__ out, int n4)
{
    int i = blockIdx.x * 256 + threadIdx.x;
    if (i >= n4) return;
    float4 v = in[i];
    __half2 h0 = __floats2half2_rn(v.x, v.y);
    __half2 h1 = __floats2half2_rn(v.z, v.w);
    uint2 r;
    r.x = *(uint32_t*)&h0;
    r.y = *(uint32_t*)&h1;
    out[i] = r;
}

// ======================= single-pass fp16 GEMM =============================
// C[M,N] = A[M,K] * B[N,K]^T, fp16 operands, fp32 accumulate.
// 128x128 CTA tile, 4 warps of 64x64, BK=64 halves (128B rows), 2-stage
// cp.async, SW128 swizzle, ldmatrix fragments. 2 CTAs/SM.
#define H_STAGE_BYTES 32768
#define H_SMEM_BYTES  (2 * H_STAGE_BYTES)   // 65536

__device__ __forceinline__ void h_load_stage(uint32_t sbase, const char* gA,
                                             const char* gB, int k0, int t)
{
    const char* gs[2] = {gA, gB};
#pragma unroll
    for (int ts = 0; ts < 2; ++ts) {
        const char* g = gs[ts] + (size_t)k0 * 2;   // k0 halves -> bytes
        uint32_t tb = sbase + ts * 16384;
#pragma unroll
        for (int i = 0; i < 8; ++i) {
            int c = t + i * 128;              // 0..1023 chunks
            int row = c >> 3, cc = c & 7;
            uint32_t off = row * 128 + cc * 16;
            uint32_t sw = off ^ ((off >> 3) & 0x70);
            cp16(tb + sw, g + (size_t)row * (K_ * 2) + cc * 16);
        }
    }
    cp_commit();
}

__global__ __launch_bounds__(128, 2)
void gemm_fp16(const __half* __restrict__ A, const __half* __restrict__ B,
               float* __restrict__ C, int N)
{
    extern __shared__ __align__(1024) char smem_raw[];
    const int t    = threadIdx.x;
    const int wid  = t >> 5;                 // 0..3
    const int lane = t & 31;
    const int g    = lane >> 2;
    const int c    = lane & 3;
    const int m0w  = (wid >> 1) * 64;        // 0 / 64
    const int n0w  = (wid & 1) * 64;         // 0 / 64
    const int rowBase = blockIdx.y << 7;
    const int colBase = blockIdx.x << 7;

    uint32_t sb = s2u(smem_raw);

    // ldmatrix lane geometry (b16 8x8 matrices, 16B rows)
    const int a_row = (lane & 7) + ((lane >> 3) & 1) * 8;   // A: row within m16
    const int a_cb  = (lane >> 4) * 16;                     // A: k-half byte offset
    const int b_row = (lane & 7) + ((lane >> 4) & 1) * 8;   // B: row within nb-pair
    const int b_cb  = ((lane >> 3) & 1) * 16;               // B: k-half byte offset
    const uint32_t xort = (uint32_t)(lane & 7) << 4;        // swizzle XOR

    uint32_t abase[4], bbase[4];
#pragma unroll
    for (int mb = 0; mb < 4; ++mb)
        abase[mb] = (uint32_t)(m0w + mb * 16 + a_row) * 128 + a_cb;
#pragma unroll
    for (int nbp = 0; nbp < 4; ++nbp)
        bbase[nbp] = (uint32_t)(n0w + nbp * 16 + b_row) * 128 + b_cb;

    float acc[4][8][4];
#pragma unroll
    for (int mb = 0; mb < 4; ++mb)
#pragma unroll
        for (int nb = 0; nb < 8; ++nb)
#pragma unroll
            for (int r = 0; r < 4; ++r) acc[mb][nb][r] = 0.f;

    const char* gA = (const char*)A + (size_t)rowBase * K_ * 2;
    const char* gB = (const char*)B + (size_t)colBase * K_ * 2;

    const int NT = K_ / 64;   // 32 k-tiles (BK=64 halves)

    h_load_stage(sb, gA, gB, 0, t);
    cp_wait0();
    __syncthreads();

    for (int kt = 0; kt < NT; ++kt) {
        const int s = kt & 1;
        if (kt + 1 < NT)
            h_load_stage(sb + (s ^ 1) * H_STAGE_BYTES, gA, gB, (kt + 1) << 6, t);
        const uint32_t stA = sb + s * H_STAGE_BYTES;
        const uint32_t stB = stA + 16384;

#pragma unroll
        for (int ks = 0; ks < 4; ++ks) {           // 4 x k16
            const uint32_t ko = (uint32_t)ks * 32; // 16 halves = 32 bytes
            uint32_t a[4][4], bfr[8][2];
#pragma unroll
            for (int mb = 0; mb < 4; ++mb)
                ldsm_x4(a[mb], stA + ((abase[mb] + ko) ^ xort));
#pragma unroll
            for (int nbp = 0; nbp < 4; ++nbp) {
                uint32_t r[4];
                ldsm_x4(r, stB + ((bbase[nbp] + ko) ^ xort));
                bfr[2 * nbp][0]     = r[0];
                bfr[2 * nbp][1]     = r[1];
                bfr[2 * nbp + 1][0] = r[2];
                bfr[2 * nbp + 1][1] = r[3];
            }
#pragma unroll
            for (int mb = 0; mb < 4; ++mb)
#pragma unroll
                for (int nb = 0; nb < 8; ++nb)
                    mma_fp16(acc[mb][nb], a[mb], bfr[nb]);
        }
        if (kt + 1 < NT) cp_wait0();
        __syncthreads();
    }

#pragma unroll
    for (int mb = 0; mb < 4; ++mb)
#pragma unroll
        for (int nb = 0; nb < 8; ++nb) {
            int row = rowBase + m0w + mb * 16 + g;
            int col = colBase + n0w + nb * 8 + 2 * c;
            float2 v0 = {acc[mb][nb][0], acc[mb][nb][1]};
            float2 v1 = {acc[mb][nb][2], acc[mb][nb][3]};
            *(float2*)(C + (size_t)row * N + col)       = v0;
            *(float2*)(C + (size_t)(row + 8) * N + col) = v1;
        }
}

// ---------------------------------------------------------------------------
// RoPE + unit-norm + q*attn_scale; tf32-rounded q/k/v in [b,h,s,hd].
// ---------------------------------------------------------------------------
__global__ __launch_bounds__(64)
void rope_norm_kernel(const float* __restrict__ qkv,
                      const float* __restrict__ freqs,
                      const float* __restrict__ scale_p,
                      float* __restrict__ gq, float* __restrict__ gk,
                      float* __restrict__ gv)
{
    const int idx = blockIdx.x;
    const int h = idx % H_;
    const int s = (idx / H_) % S_;
    const int b = idx / (H_ * S_);
    const int i = threadIdx.x;

    const float* base = qkv + (size_t)(b * S_ + s) * NQKV + h * HD_;
    float q0 = base[2 * i],           q1 = base[2 * i + 1];
    float k0 = base[D_ + 2 * i],      k1 = base[D_ + 2 * i + 1];
    float v0 = base[2 * D_ + 2 * i],  v1 = base[2 * D_ + 2 * i + 1];

    float cs = freqs[((size_t)s * 64 + i) * 2 + 0];
    float sn = freqs[((size_t)s * 64 + i) * 2 + 1];

    float qr = q0 * cs - q1 * sn, qi = q0 * sn + q1 * cs;
    float kr = k0 * cs - k1 * sn, ki = k0 * sn + k1 * cs;

    float sq = qr * qr + qi * qi;
    float sk = kr * kr + ki * ki;
#pragma unroll
    for (int off = 16; off > 0; off >>= 1) {
        sq += __shfl_xor_sync(0xffffffffu, sq, off);
        sk += __shfl_xor_sync(0xffffffffu, sk, off);
    }
    __shared__ float smq[2], smk[2];
    if ((i & 31) == 0) { smq[i >> 5] = sq; smk[i >> 5] = sk; }
    __syncthreads();
    float nq = sqrtf(smq[0] + smq[1]) + 1e-6f;
    float nk = sqrtf(smk[0] + smk[1]) + 1e-6f;

    float scl = *scale_p;
    float qs = scl / nq;
    float ks = 1.0f / nk;

    size_t o = ((size_t)(b * H_ + h) * S_ + s) * HD_;
    gq[o + 2 * i] = tf32r(qr * qs);  gq[o + 2 * i + 1] = tf32r(qi * qs);
    gk[o + 2 * i] = tf32r(kr * ks);  gk[o + 2 * i + 1] = tf32r(ki * ks);
    gv[o + 2 * i] = tf32r(v0);       gv[o + 2 * i + 1] = tf32r(v1);
}

// ---------------------------------------------------------------------------
// tf32 flash attention (R8 structure). BM=128, BN=64, 256 threads.
// Epilogue writes fp16 attn for the fp16 GEMM2.
// ---------------------------------------------------------------------------
#define QS_OFF 0
#define KS_OFF (128 * 132)
#define KS_BUF (64 * 132)
#define VS_OFF (KS_OFF + 2 * KS_BUF)
#define PS_OFF (VS_OFF + 64 * 136)
#define AT_SMEM_FLOATS (PS_OFF + 128 * 68)
#define AT_SMEM_BYTES (AT_SMEM_FLOATS * 4)    // 204800

__global__ __launch_bounds__(256)
void flash_tc(const float* __restrict__ gq, const float* __restrict__ gk,
              const float* __restrict__ gv, __half* __restrict__ gout)
{
    extern __shared__ float sm[];
    uint32_t smb = s2u(sm);
    const int t    = threadIdx.x;
    const int w    = t >> 5;
    const int lane = t & 31;
    const int g    = lane >> 2;
    const int c    = lane & 3;
    const int qt   = (gridDim.x - 1) - blockIdx.x;   // heavy tiles first
    const int bh   = blockIdx.y;
    const int b    = bh >> 4;
    const int h    = bh & 15;
    const int qr0  = w * 16;

    const float* Qg = gq + ((size_t)bh * S_ + qt * 128) * HD_;
    const float* Kg = gk + (size_t)bh * S_ * HD_;
    const float* Vg = gv + (size_t)bh * S_ * HD_;

#pragma unroll
    for (int i = 0; i < 16; ++i) {
        int ci = t + i * 256;
        int row = ci >> 5, cc = ci & 31;
        cp16(smb + (QS_OFF + row * 132 + cc * 4) * 4, Qg + row * HD_ + cc * 4);
    }
    cp_commit();

    const int nkv = 2 * qt + 2;

#pragma unroll
    for (int i = 0; i < 8; ++i) {
        int ci = t + i * 256;
        int row = ci >> 5, cc = ci & 31;
        cp16(smb + (KS_OFF + row * 132 + cc * 4) * 4, Kg + (size_t)row * HD_ + cc * 4);
    }
    cp_commit();
#pragma unroll
    for (int i = 0; i < 8; ++i) {
        int ci = t + i * 256;
        int row = ci >> 5, cc = ci & 31;
        cp16(smb + (VS_OFF + row * 136 + cc * 4) * 4, Vg + (size_t)row * HD_ + cc * 4);
    }
    cp_commit();

    float O[16][4];
#pragma unroll
    for (int nb = 0; nb < 16; ++nb)
#pragma unroll
        for (int r = 0; r < 4; ++r) O[nb][r] = 0.f;
    float m0 = -1e30f, m1 = -1e30f, l0 = 0.f, l1 = 0.f;

    for (int kt = 0; kt < nkv; ++kt) {
        cp_wait1();
        __syncthreads();

        if (kt + 1 < nkv) {
            const float* ksrc = Kg + (size_t)(kt + 1) * 64 * HD_;
            uint32_t kdst = smb + (KS_OFF + ((kt + 1) & 1) * KS_BUF) * 4;
#pragma unroll
            for (int i = 0; i < 8; ++i) {
                int ci = t + i * 256;
                int row = ci >> 5, cc = ci & 31;
                cp16(kdst + (row * 132 + cc * 4) * 4, ksrc + (size_t)row * HD_ + cc * 4);
            }
            cp_commit();
        }

        const int kbase = KS_OFF + (kt & 1) * KS_BUF;
        float sacc[8][4];
#pragma unroll
        for (int nb = 0; nb < 8; ++nb)
#pragma unroll
            for (int r = 0; r < 4; ++r) sacc[nb][r] = 0.f;

#pragma unroll
        for (int ks = 0; ks < 16; ++ks) {
            const int k0 = ks * 8;
            uint32_t a[4];
            a[0] = __float_as_uint(sm[QS_OFF + (qr0 + g) * 132 + k0 + c]);
            a[1] = __float_as_uint(sm[QS_OFF + (qr0 + g + 8) * 132 + k0 + c]);
            a[2] = __float_as_uint(sm[QS_OFF + (qr0 + g) * 132 + k0 + c + 4]);
            a[3] = __float_as_uint(sm[QS_OFF + (qr0 + g + 8) * 132 + k0 + c + 4]);
#pragma unroll
            for (int nb = 0; nb < 8; ++nb) {
                uint32_t bfr[2];
                bfr[0] = __float_as_uint(sm[kbase + (nb * 8 + g) * 132 + k0 + c]);
                bfr[1] = __float_as_uint(sm[kbase + (nb * 8 + g) * 132 + k0 + c + 4]);
                mma_tf32(sacc[nb], a, bfr);
            }
        }

        if (kt >= 2 * qt) {
            int rg0 = qt * 128 + qr0 + g;
#pragma unroll
            for (int nb = 0; nb < 8; ++nb) {
                int col = kt * 64 + nb * 8 + 2 * c;
                if (col     > rg0)     sacc[nb][0] = -1e30f;
                if (col + 1 > rg0)     sacc[nb][1] = -1e30f;
                if (col     > rg0 + 8) sacc[nb][2] = -1e30f;
                if (col + 1 > rg0 + 8) sacc[nb][3] = -1e30f;
            }
        }

        float rm0 = -1e30f, rm1 = -1e30f;
#pragma unroll
        for (int nb = 0; nb < 8; ++nb) {
            rm0 = fmaxf(rm0, fmaxf(sacc[nb][0], sacc[nb][1]));
            rm1 = fmaxf(rm1, fmaxf(sacc[nb][2], sacc[nb][3]));
        }
        rm0 = fmaxf(rm0, __shfl_xor_sync(0xffffffffu, rm0, 1));
        rm0 = fmaxf(rm0, __shfl_xor_sync(0xffffffffu, rm0, 2));
        rm1 = fmaxf(rm1, __shfl_xor_sync(0xffffffffu, rm1, 1));
        rm1 = fmaxf(rm1, __shfl_xor_sync(0xffffffffu, rm1, 2));
        float mn0 = fmaxf(m0, rm0), mn1 = fmaxf(m1, rm1);
        float al0 = __expf(m0 - mn0), al1 = __expf(m1 - mn1);
        float rs0 = 0.f, rs1 = 0.f;
#pragma unroll
        for (int nb = 0; nb < 8; ++nb) {
            sacc[nb][0] = __expf(sacc[nb][0] - mn0);
            sacc[nb][1] = __expf(sacc[nb][1] - mn0);
            sacc[nb][2] = __expf(sacc[nb][2] - mn1);
            sacc[nb][3] = __expf(sacc[nb][3] - mn1);
            rs0 += sacc[nb][0] + sacc[nb][1];
            rs1 += sacc[nb][2] + sacc[nb][3];
        }
        rs0 += __shfl_xor_sync(0xffffffffu, rs0, 1);
        rs0 += __shfl_xor_sync(0xffffffffu, rs0, 2);
        rs1 += __shfl_xor_sync(0xffffffffu, rs1, 1);
        rs1 += __shfl_xor_sync(0xffffffffu, rs1, 2);
        l0 = l0 * al0 + rs0;  m0 = mn0;
        l1 = l1 * al1 + rs1;  m1 = mn1;
#pragma unroll
        for (int nb = 0; nb < 16; ++nb) {
            O[nb][0] *= al0; O[nb][1] *= al0;
            O[nb][2] *= al1; O[nb][3] *= al1;
        }

#pragma unroll
        for (int nb = 0; nb < 8; ++nb) {
            int colp = nb * 8 + 2 * c;
            sm[PS_OFF + (qr0 + g) * 68 + colp]         = tf32r(sacc[nb][0]);
            sm[PS_OFF + (qr0 + g) * 68 + colp + 1]     = tf32r(sacc[nb][1]);
            sm[PS_OFF + (qr0 + g + 8) * 68 + colp]     = tf32r(sacc[nb][2]);
            sm[PS_OFF + (qr0 + g + 8) * 68 + colp + 1] = tf32r(sacc[nb][3]);
        }
        __syncwarp();

        if (kt + 1 < nkv) cp_wait1(); else cp_wait0();
        __syncthreads();

#pragma unroll
        for (int ks = 0; ks < 8; ++ks) {
            const int k0 = ks * 8;
            uint32_t a[4];
            a[0] = __float_as_uint(sm[PS_OFF + (qr0 + g) * 68 + k0 + c]);
            a[1] = __float_as_uint(sm[PS_OFF + (qr0 + g + 8) * 68 + k0 + c]);
            a[2] = __float_as_uint(sm[PS_OFF + (qr0 + g) * 68 + k0 + c + 4]);
            a[3] = __float_as_uint(sm[PS_OFF + (qr0 + g + 8) * 68 + k0 + c + 4]);
#pragma unroll
            for (int nb = 0; nb < 16; ++nb) {
                uint32_t bfr[2];
                bfr[0] = __float_as_uint(sm[VS_OFF + (k0 + c) * 136 + nb * 8 + g]);
                bfr[1] = __float_as_uint(sm[VS_OFF + (k0 + c + 4) * 136 + nb * 8 + g]);
                mma_tf32(O[nb], a, bfr);
            }
        }
        __syncthreads();

        if (kt + 1 < nkv) {
            const float* vsrc = Vg + (size_t)(kt + 1) * 64 * HD_;
#pragma unroll
            for (int i = 0; i < 8; ++i) {
                int ci = t + i * 256;
                int row = ci >> 5, cc = ci & 31;
                cp16(smb + (VS_OFF + row * 136 + cc * 4) * 4,
                     vsrc + (size_t)row * HD_ + cc * 4);
            }
            cp_commit();
        }
    }

    // ---- epilogue: fp16 attn ([b,s,h,hd]) ----
    float inv0 = 1.f / l0, inv1 = 1.f / l1;
    int r0 = qt * 128 + qr0 + g;
    int r1 = r0 + 8;
#pragma unroll
    for (int nb = 0; nb < 16; ++nb) {
        int d = nb * 8 + 2 * c;
        __half2 h0 = __floats2half2_rn(O[nb][0] * inv0, O[nb][1] * inv0);
        __half2 h1 = __floats2half2_rn(O[nb][2] * inv1, O[nb][3] * inv1);
        *(__half2*)(gout + ((size_t)(b * S_ + r0) * H_ + h) * HD_ + d) = h0;
        *(__half2*)(gout + ((size_t)(b * S_ + r1) * H_ + h) * HD_ + d) = h1;
    }
}

// ---------------------------------------------------------------------------
extern "C" void kernel_launch(void* const* d_in, const int* in_sizes, int n_in,
                              void* d_out, int out_size)
{
    const float* x      = (const float*)d_in[0];
    const float* freqs  = (const float*)d_in[1];
    const float* wqkv   = (const float*)d_in[2];
    const float* wout   = (const float*)d_in[3];
    const float* ascale = (const float*)d_in[4];
    float* out = (float*)d_out;

    float *qkv, *q, *k, *v;
    __half *xh, *wqh, *woh, *atth;
    cudaGetSymbolAddress((void**)&qkv,  g_qkv);
    cudaGetSymbolAddress((void**)&q,    g_q);
    cudaGetSymbolAddress((void**)&k,    g_k);
    cudaGetSymbolAddress((void**)&v,    g_v);
    cudaGetSymbolAddress((void**)&xh,   g_xh);
    cudaGetSymbolAddress((void**)&wqh,  g_wqh);
    cudaGetSymbolAddress((void**)&woh,  g_woh);
    cudaGetSymbolAddress((void**)&atth, g_atth);

    cudaFuncSetAttribute(gemm_fp16, cudaFuncAttributeMaxDynamicSharedMemorySize,
                         H_SMEM_BYTES);
    cudaFuncSetAttribute(flash_tc, cudaFuncAttributeMaxDynamicSharedMemorySize,
                         AT_SMEM_BYTES);

    // 0) fp16(RN) convert GEMM operands
    {
        int n4 = (M_ * D_) / 4;
        to_half<<<(n4 + 255) / 256, 256>>>((const float4*)x, (uint2*)xh, n4);
    }
    {
        int n4 = (NQKV * D_) / 4;
        to_half<<<(n4 + 255) / 256, 256>>>((const float4*)wqkv, (uint2*)wqh, n4);
    }
    {
        int n4 = (D_ * D_) / 4;
        to_half<<<(n4 + 255) / 256, 256>>>((const float4*)wout, (uint2*)woh, n4);
    }

    // 1) qkv = x @ w_qkv^T  (single-pass fp16 HMMA, fp32 accum)
    gemm_fp16<<<dim3(NQKV / 128, M_ / 128), 128, H_SMEM_BYTES>>>(xh, wqh, qkv, NQKV);

    // 2) RoPE + norm + scale (tf32-rounded outputs)
    rope_norm_kernel<<<B_ * S_ * H_, 64>>>(qkv, freqs, ascale, q, k, v);

    // 3) flash attention -> fp16 attn [b,s,h,hd]
    flash_tc<<<dim3(S_ / 128, B_ * H_), 256, AT_SMEM_BYTES>>>(q, k, v, atth);

    // 4) out = attn @ w_out^T  (single-pass fp16 HMMA)
    gemm_fp16<<<dim3(D_ / 128, M_ / 128), 128, H_SMEM_BYTES>>>(atth, woh, out, D_);
}

// round 16
// speedup vs baseline: 1.8081x; 1.2676x over previous
#include <cuda_runtime.h>
#include <cuda_fp16.h>
#include <math.h>
#include <stdint.h>

// Problem constants
#define B_   2
#define S_   2048
#define D_   2048
#define H_   16
#define HD_  128
#define M_   (B_ * S_)      // 4096
#define NQKV (3 * D_)       // 6144
#define K_   D_             // 2048

// ---------------- scratch (device globals) ---------------------------------
__device__ float g_qkv[(size_t)M_ * NQKV];

__device__ __align__(1024) __half g_xh  [(size_t)M_ * D_];     // x fp16
__device__ __align__(1024) __half g_wqh [(size_t)NQKV * D_];   // w_qkv fp16
__device__ __align__(1024) __half g_woh [(size_t)D_ * D_];     // w_out fp16
__device__ __align__(1024) __half g_atth[(size_t)M_ * D_];     // attn fp16 [b,s,h,hd]
__device__ __align__(1024) __half g_qh  [(size_t)M_ * D_];     // q fp16 [b,h,s,hd]
__device__ __align__(1024) __half g_kh  [(size_t)M_ * D_];
__device__ __align__(1024) __half g_vh  [(size_t)M_ * D_];

// ======================= PTX helpers (compute_103-safe) =====================
__device__ __forceinline__ uint32_t s2u(const void* p) {
    uint32_t a;
    asm("{ .reg .u64 t; cvta.to.shared.u64 t, %1; cvt.u32.u64 %0, t; }"
        : "=r"(a) : "l"(p));
    return a;
}
__device__ __forceinline__ void cp16(uint32_t dst, const void* src) {
    asm volatile("cp.async.ca.shared.global [%0], [%1], 16;" :: "r"(dst), "l"(src));
}
__device__ __forceinline__ void cp_commit() {
    asm volatile("cp.async.commit_group;" ::: "memory");
}
__device__ __forceinline__ void cp_wait0() {
    asm volatile("cp.async.wait_group 0;" ::: "memory");
}
__device__ __forceinline__ void cp_wait1() {
    asm volatile("cp.async.wait_group 1;" ::: "memory");
}
__device__ __forceinline__ void ldsm_x4(uint32_t* r, uint32_t addr) {
    asm volatile("ldmatrix.sync.aligned.m8n8.x4.shared.b16 {%0,%1,%2,%3}, [%4];"
                 : "=r"(r[0]), "=r"(r[1]), "=r"(r[2]), "=r"(r[3]) : "r"(addr));
}
__device__ __forceinline__ void ldsm_x4t(uint32_t* r, uint32_t addr) {
    asm volatile("ldmatrix.sync.aligned.m8n8.x4.trans.shared.b16 {%0,%1,%2,%3}, [%4];"
                 : "=r"(r[0]), "=r"(r[1]), "=r"(r[2]), "=r"(r[3]) : "r"(addr));
}
__device__ __forceinline__ void mma_fp16(float* d, const uint32_t* a, const uint32_t* b) {
    asm volatile(
        "mma.sync.aligned.m16n8k16.row.col.f32.f16.f16.f32 "
        "{%0,%1,%2,%3}, {%4,%5,%6,%7}, {%8,%9}, {%0,%1,%2,%3};"
        : "+f"(d[0]), "+f"(d[1]), "+f"(d[2]), "+f"(d[3])
        : "r"(a[0]), "r"(a[1]), "r"(a[2]), "r"(a[3]), "r"(b[0]), "r"(b[1]));
}

// ======================= fp32 -> fp16(rn) convert ==========================
__global__ __launch_bounds__(256)
void to_half(const float4* __restrict__ in, uint2* __restrict__ out, int n4)
{
    int i = blockIdx.x * 256 + threadIdx.x;
    if (i >= n4) return;
    float4 v = in[i];
    __half2 h0 = __floats2half2_rn(v.x, v.y);
    __half2 h1 = __floats2half2_rn(v.z, v.w);
    uint2 r;
    r.x = *(uint32_t*)&h0;
    r.y = *(uint32_t*)&h1;
    out[i] = r;
}

// ======================= single-pass fp16 GEMM (R14, unchanged) ============
#define H_STAGE_BYTES 32768
#define H_SMEM_BYTES  (2 * H_STAGE_BYTES)   // 65536

__device__ __forceinline__ void h_load_stage(uint32_t sbase, const char* gA,
                                             const char* gB, int k0, int t)
{
    const char* gs[2] = {gA, gB};
#pragma unroll
    for (int ts = 0; ts < 2; ++ts) {
        const char* g = gs[ts] + (size_t)k0 * 2;
        uint32_t tb = sbase + ts * 16384;
#pragma unroll
        for (int i = 0; i < 8; ++i) {
            int c = t + i * 128;
            int row = c >> 3, cc = c & 7;
            uint32_t off = row * 128 + cc * 16;
            uint32_t sw = off ^ ((off >> 3) & 0x70);
            cp16(tb + sw, g + (size_t)row * (K_ * 2) + cc * 16);
        }
    }
    cp_commit();
}

__global__ __launch_bounds__(128, 2)
void gemm_fp16(const __half* __restrict__ A, const __half* __restrict__ B,
               float* __restrict__ C, int N)
{
    extern __shared__ __align__(1024) char smem_raw[];
    const int t    = threadIdx.x;
    const int wid  = t >> 5;
    const int lane = t & 31;
    const int g    = lane >> 2;
    const int c    = lane & 3;
    const int m0w  = (wid >> 1) * 64;
    const int n0w  = (wid & 1) * 64;
    const int rowBase = blockIdx.y << 7;
    const int colBase = blockIdx.x << 7;

    uint32_t sb = s2u(smem_raw);

    const int a_row = (lane & 7) + ((lane >> 3) & 1) * 8;
    const int a_cb  = (lane >> 4) * 16;
    const int b_row = (lane & 7) + ((lane >> 4) & 1) * 8;
    const int b_cb  = ((lane >> 3) & 1) * 16;
    const uint32_t xort = (uint32_t)(lane & 7) << 4;

    uint32_t abase[4], bbase[4];
#pragma unroll
    for (int mb = 0; mb < 4; ++mb)
        abase[mb] = (uint32_t)(m0w + mb * 16 + a_row) * 128 + a_cb;
#pragma unroll
    for (int nbp = 0; nbp < 4; ++nbp)
        bbase[nbp] = (uint32_t)(n0w + nbp * 16 + b_row) * 128 + b_cb;

    float acc[4][8][4];
#pragma unroll
    for (int mb = 0; mb < 4; ++mb)
#pragma unroll
        for (int nb = 0; nb < 8; ++nb)
#pragma unroll
            for (int r = 0; r < 4; ++r) acc[mb][nb][r] = 0.f;

    const char* gA = (const char*)A + (size_t)rowBase * K_ * 2;
    const char* gB = (const char*)B + (size_t)colBase * K_ * 2;

    const int NT = K_ / 64;

    h_load_stage(sb, gA, gB, 0, t);
    cp_wait0();
    __syncthreads();

    for (int kt = 0; kt < NT; ++kt) {
        const int s = kt & 1;
        if (kt + 1 < NT)
            h_load_stage(sb + (s ^ 1) * H_STAGE_BYTES, gA, gB, (kt + 1) << 6, t);
        const uint32_t stA = sb + s * H_STAGE_BYTES;
        const uint32_t stB = stA + 16384;

#pragma unroll
        for (int ks = 0; ks < 4; ++ks) {
            const uint32_t ko = (uint32_t)ks * 32;
            uint32_t a[4][4], bfr[8][2];
#pragma unroll
            for (int mb = 0; mb < 4; ++mb)
                ldsm_x4(a[mb], stA + ((abase[mb] + ko) ^ xort));
#pragma unroll
            for (int nbp = 0; nbp < 4; ++nbp) {
                uint32_t r[4];
                ldsm_x4(r, stB + ((bbase[nbp] + ko) ^ xort));
                bfr[2 * nbp][0]     = r[0];
                bfr[2 * nbp][1]     = r[1];
                bfr[2 * nbp + 1][0] = r[2];
                bfr[2 * nbp + 1][1] = r[3];
            }
#pragma unroll
            for (int mb = 0; mb < 4; ++mb)
#pragma unroll
                for (int nb = 0; nb < 8; ++nb)
                    mma_fp16(acc[mb][nb], a[mb], bfr[nb]);
        }
        if (kt + 1 < NT) cp_wait0();
        __syncthreads();
    }

#pragma unroll
    for (int mb = 0; mb < 4; ++mb)
#pragma unroll
        for (int nb = 0; nb < 8; ++nb) {
            int row = rowBase + m0w + mb * 16 + g;
            int col = colBase + n0w + nb * 8 + 2 * c;
            float2 v0 = {acc[mb][nb][0], acc[mb][nb][1]};
            float2 v1 = {acc[mb][nb][2], acc[mb][nb][3]};
            *(float2*)(C + (size_t)row * N + col)       = v0;
            *(float2*)(C + (size_t)(row + 8) * N + col) = v1;
        }
}

// ---------------------------------------------------------------------------
// RoPE + unit-norm + q*attn_scale; fp16 q/k/v in [b,h,s,hd].
// ---------------------------------------------------------------------------
__global__ __launch_bounds__(64)
void rope_norm_kernel(const float* __restrict__ qkv,
                      const float* __restrict__ freqs,
                      const float* __restrict__ scale_p,
                      __half* __restrict__ gq, __half* __restrict__ gk,
                      __half* __restrict__ gv)
{
    const int idx = blockIdx.x;
    const int h = idx % H_;
    const int s = (idx / H_) % S_;
    const int b = idx / (H_ * S_);
    const int i = threadIdx.x;

    const float* base = qkv + (size_t)(b * S_ + s) * NQKV + h * HD_;
    float q0 = base[2 * i],           q1 = base[2 * i + 1];
    float k0 = base[D_ + 2 * i],      k1 = base[D_ + 2 * i + 1];
    float v0 = base[2 * D_ + 2 * i],  v1 = base[2 * D_ + 2 * i + 1];

    float cs = freqs[((size_t)s * 64 + i) * 2 + 0];
    float sn = freqs[((size_t)s * 64 + i) * 2 + 1];

    float qr = q0 * cs - q1 * sn, qi = q0 * sn + q1 * cs;
    float kr = k0 * cs - k1 * sn, ki = k0 * sn + k1 * cs;

    float sq = qr * qr + qi * qi;
    float sk = kr * kr + ki * ki;
#pragma unroll
    for (int off = 16; off > 0; off >>= 1) {
        sq += __shfl_xor_sync(0xffffffffu, sq, off);
        sk += __shfl_xor_sync(0xffffffffu, sk, off);
    }
    __shared__ float smq[2], smk[2];
    if ((i & 31) == 0) { smq[i >> 5] = sq; smk[i >> 5] = sk; }
    __syncthreads();
    float nq = sqrtf(smq[0] + smq[1]) + 1e-6f;
    float nk = sqrtf(smk[0] + smk[1]) + 1e-6f;

    float scl = *scale_p;
    float qs = scl / nq;
    float ks = 1.0f / nk;

    size_t o = ((size_t)(b * H_ + h) * S_ + s) * HD_ + 2 * i;
    *(__half2*)(gq + o) = __floats2half2_rn(qr * qs, qi * qs);
    *(__half2*)(gk + o) = __floats2half2_rn(kr * ks, ki * ks);
    *(__half2*)(gv + o) = __floats2half2_rn(v0, v1);
}

// ---------------------------------------------------------------------------
// fp16 flash attention. BM=128, BN=64, HD=128, 256 threads.
// Tiles stored as d-panels of 128B rows, SW128 swizzle.
// smem bytes: Q @0 (32KB: 2 panels x 16KB), K[2] @32K (2x16KB),
//             V @64K (16KB), P @80K (16KB).  Total 96KB.
// ---------------------------------------------------------------------------
#define FQ_OFF 0
#define FQ_PAN 16384
#define FK_OFF 32768
#define FK_BUF 16384
#define FV_OFF 65536
#define FP_OFF 81920
#define F_SMEM_BYTES 98304

__global__ __launch_bounds__(256)
void flash_fp16(const __half* __restrict__ gq, const __half* __restrict__ gk,
                const __half* __restrict__ gv, __half* __restrict__ gout)
{
    extern __shared__ __align__(1024) char fsm[];
    uint32_t smb = s2u(fsm);
    const int t    = threadIdx.x;
    const int w    = t >> 5;
    const int lane = t & 31;
    const int g    = lane >> 2;
    const int c    = lane & 3;
    const int qt   = (gridDim.x - 1) - blockIdx.x;   // heavy tiles first
    const int bh   = blockIdx.y;
    const int b    = bh >> 4;
    const int h    = bh & 15;
    const int qr0  = w * 16;

    const char* Qg = (const char*)(gq + ((size_t)bh * S_ + qt * 128) * HD_);
    const char* Kg = (const char*)(gk + (size_t)bh * S_ * HD_);
    const char* Vg = (const char*)(gv + (size_t)bh * S_ * HD_);

    // fragment lane geometry
    const int a_row = (lane & 7) + ((lane >> 3) & 1) * 8;
    const int a_cb  = (lane >> 4) * 16;
    const int b_row = (lane & 7) + ((lane >> 4) & 1) * 8;
    const int b_cb  = ((lane >> 3) & 1) * 16;
    const uint32_t xort = (uint32_t)(lane & 7) << 4;
    // V trans-load per-lane base: row = kp*16 + ((l>>3)&1)*8 + (l&7), col16 = ((l>>4)&1)*16
    const uint32_t vlbase = (uint32_t)(((lane >> 3) & 1) * 8 + (lane & 7)) * 128
                          + ((lane >> 4) & 1) * 16;

    const uint32_t aqbase = (uint32_t)(qr0 + a_row) * 128 + a_cb;   // Q/P A-frag base
    uint32_t bkbase[4];
#pragma unroll
    for (int nbp = 0; nbp < 4; ++nbp)
        bkbase[nbp] = (uint32_t)(nbp * 16 + b_row) * 128 + b_cb;    // K B-frag

    // ---- prologue loads: Q (group), K0 (group), V0 (group) ----
#pragma unroll
    for (int i = 0; i < 8; ++i) {               // Q: 128 rows x 256B = 2048 chunks
        int ci = t + i * 256;
        int row = ci >> 4, sub = ci & 15;
        uint32_t off = row * 128 + (sub & 7) * 16;
        uint32_t sw = off ^ ((off >> 3) & 0x70);
        cp16(smb + FQ_OFF + (sub >> 3) * FQ_PAN + sw, Qg + (size_t)row * 256 + sub * 16);
    }
    cp_commit();

    const int nkv = 2 * qt + 2;

#pragma unroll
    for (int i = 0; i < 4; ++i) {               // K0: 64 rows x 256B = 1024 chunks
        int ci = t + i * 256;
        int row = ci >> 4, sub = ci & 15;
        uint32_t off = row * 128 + (sub & 7) * 16;
        uint32_t sw = off ^ ((off >> 3) & 0x70);
        cp16(smb + FK_OFF + (sub >> 3) * 8192 + sw, Kg + (size_t)row * 256 + sub * 16);
    }
    cp_commit();
#pragma unroll
    for (int i = 0; i < 4; ++i) {               // V0
        int ci = t + i * 256;
        int row = ci >> 4, sub = ci & 15;
        uint32_t off = row * 128 + (sub & 7) * 16;
        uint32_t sw = off ^ ((off >> 3) & 0x70);
        cp16(smb + FV_OFF + (sub >> 3) * 8192 + sw, Vg + (size_t)row * 256 + sub * 16);
    }
    cp_commit();

    float O[16][4];
#pragma unroll
    for (int nb = 0; nb < 16; ++nb)
#pragma unroll
        for (int r = 0; r < 4; ++r) O[nb][r] = 0.f;
    float m0 = -1e30f, m1 = -1e30f, l0 = 0.f, l1 = 0.f;

    for (int kt = 0; kt < nkv; ++kt) {
        cp_wait1();              // Q+K[kt] complete (V[kt] may be in flight)
        __syncthreads();

        if (kt + 1 < nkv) {      // prefetch K[kt+1]
            const char* ksrc = Kg + (size_t)(kt + 1) * 64 * 256;
            uint32_t kdst = smb + FK_OFF + ((kt + 1) & 1) * FK_BUF;
#pragma unroll
            for (int i = 0; i < 4; ++i) {
                int ci = t + i * 256;
                int row = ci >> 4, sub = ci & 15;
                uint32_t off = row * 128 + (sub & 7) * 16;
                uint32_t sw = off ^ ((off >> 3) & 0x70);
                cp16(kdst + (sub >> 3) * 8192 + sw, ksrc + (size_t)row * 256 + sub * 16);
            }
            cp_commit();
        }

        // ---- S = Q K^T (fp16 mma, 8 k16 steps) ----
        const uint32_t kbuf = smb + FK_OFF + (kt & 1) * FK_BUF;
        float sacc[8][4];
#pragma unroll
        for (int nb = 0; nb < 8; ++nb)
#pragma unroll
            for (int r = 0; r < 4; ++r) sacc[nb][r] = 0.f;

#pragma unroll
        for (int ks = 0; ks < 8; ++ks) {
            const uint32_t pq = (uint32_t)(ks >> 2) * FQ_PAN;   // Q panel (128-row)
            const uint32_t pk = (uint32_t)(ks >> 2) * 8192;     // K panel (64-row)
            const uint32_t ko = (uint32_t)(ks & 3) * 32;
            uint32_t a[4];
            ldsm_x4(a, smb + FQ_OFF + pq + ((aqbase + ko) ^ xort));
#pragma unroll
            for (int nbp = 0; nbp < 4; ++nbp) {
                uint32_t r[4];
                ldsm_x4(r, kbuf + pk + ((bkbase[nbp] + ko) ^ xort));
                mma_fp16(sacc[2 * nbp],     a, r);
                mma_fp16(sacc[2 * nbp + 1], a, r + 2);
            }
        }

        // ---- causal mask ----
        if (kt >= 2 * qt) {
            int rg0 = qt * 128 + qr0 + g;
#pragma unroll
            for (int nb = 0; nb < 8; ++nb) {
                int col = kt * 64 + nb * 8 + 2 * c;
                if (col     > rg0)     sacc[nb][0] = -1e30f;
                if (col + 1 > rg0)     sacc[nb][1] = -1e30f;
                if (col     > rg0 + 8) sacc[nb][2] = -1e30f;
                if (col + 1 > rg0 + 8) sacc[nb][3] = -1e30f;
            }
        }

        // ---- online softmax ----
        float rm0 = -1e30f, rm1 = -1e30f;
#pragma unroll
        for (int nb = 0; nb < 8; ++nb) {
            rm0 = fmaxf(rm0, fmaxf(sacc[nb][0], sacc[nb][1]));
            rm1 = fmaxf(rm1, fmaxf(sacc[nb][2], sacc[nb][3]));
        }
        rm0 = fmaxf(rm0, __shfl_xor_sync(0xffffffffu, rm0, 1));
        rm0 = fmaxf(rm0, __shfl_xor_sync(0xffffffffu, rm0, 2));
        rm1 = fmaxf(rm1, __shfl_xor_sync(0xffffffffu, rm1, 1));
        rm1 = fmaxf(rm1, __shfl_xor_sync(0xffffffffu, rm1, 2));
        float mn0 = fmaxf(m0, rm0), mn1 = fmaxf(m1, rm1);
        float al0 = __expf(m0 - mn0), al1 = __expf(m1 - mn1);
        float rs0 = 0.f, rs1 = 0.f;
#pragma unroll
        for (int nb = 0; nb < 8; ++nb) {
            sacc[nb][0] = __expf(sacc[nb][0] - mn0);
            sacc[nb][1] = __expf(sacc[nb][1] - mn0);
            sacc[nb][2] = __expf(sacc[nb][2] - mn1);
            sacc[nb][3] = __expf(sacc[nb][3] - mn1);
            rs0 += sacc[nb][0] + sacc[nb][1];
            rs1 += sacc[nb][2] + sacc[nb][3];
        }
        rs0 += __shfl_xor_sync(0xffffffffu, rs0, 1);
        rs0 += __shfl_xor_sync(0xffffffffu, rs0, 2);
        rs1 += __shfl_xor_sync(0xffffffffu, rs1, 1);
        rs1 += __shfl_xor_sync(0xffffffffu, rs1, 2);
        l0 = l0 * al0 + rs0;  m0 = mn0;
        l1 = l1 * al1 + rs1;  m1 = mn1;
#pragma unroll
        for (int nb = 0; nb < 16; ++nb) {
            O[nb][0] *= al0; O[nb][1] *= al0;
            O[nb][2] *= al1; O[nb][3] *= al1;
        }

        // ---- P -> smem fp16 (swizzled 128B rows; store XOR = g<<4) ----
        {
            const uint32_t swg = (uint32_t)g << 4;
            const uint32_t r0o = (uint32_t)(qr0 + g) * 128;
            const uint32_t r1o = r0o + 8 * 128;
#pragma unroll
            for (int nb = 0; nb < 8; ++nb) {
                uint32_t colb = (uint32_t)(nb * 8 + 2 * c) * 2;
                __half2 p0 = __floats2half2_rn(sacc[nb][0], sacc[nb][1]);
                __half2 p1 = __floats2half2_rn(sacc[nb][2], sacc[nb][3]);
                *(__half2*)(fsm + FP_OFF + ((r0o + colb) ^ swg)) = p0;
                *(__half2*)(fsm + FP_OFF + ((r1o + colb) ^ swg)) = p1;
            }
        }
        __syncwarp();

        // ---- wait for V[kt] ----
        if (kt + 1 < nkv) cp_wait1(); else cp_wait0();
        __syncthreads();

        // ---- O += P V (fp16 mma, ldmatrix.trans for V) ----
#pragma unroll
        for (int kp = 0; kp < 4; ++kp) {
            const uint32_t kov = (uint32_t)kp * 16 * 128;     // V rows
            uint32_t a[4];
            ldsm_x4(a, smb + FP_OFF + ((aqbase + (uint32_t)kp * 32) ^ xort));
#pragma unroll
            for (int n16 = 0; n16 < 8; ++n16) {
                const uint32_t pan = (uint32_t)(n16 >> 2) * 8192;
                uint32_t off = vlbase + kov + (uint32_t)(n16 & 3) * 32;
                uint32_t r[4];
                ldsm_x4t(r, smb + FV_OFF + pan + (off ^ xort));
                mma_fp16(O[2 * n16],     a, r);
                mma_fp16(O[2 * n16 + 1], a, r + 2);
            }
        }
        __syncthreads();   // all reads of Vs done

        if (kt + 1 < nkv) {    // load V[kt+1]
            const char* vsrc = Vg + (size_t)(kt + 1) * 64 * 256;
#pragma unroll
            for (int i = 0; i < 4; ++i) {
                int ci = t + i * 256;
                int row = ci >> 4, sub = ci & 15;
                uint32_t off = row * 128 + (sub & 7) * 16;
                uint32_t sw = off ^ ((off >> 3) & 0x70);
                cp16(smb + FV_OFF + (sub >> 3) * 8192 + sw, vsrc + (size_t)row * 256 + sub * 16);
            }
            cp_commit();
        }
    }

    // ---- epilogue: fp16 attn ([b,s,h,hd]) ----
    float inv0 = 1.f / l0, inv1 = 1.f / l1;
    int r0 = qt * 128 + qr0 + g;
    int r1 = r0 + 8;
#pragma unroll
    for (int nb = 0; nb < 16; ++nb) {
        int d = nb * 8 + 2 * c;
        __half2 h0 = __floats2half2_rn(O[nb][0] * inv0, O[nb][1] * inv0);
        __half2 h1 = __floats2half2_rn(O[nb][2] * inv1, O[nb][3] * inv1);
        *(__half2*)(gout + ((size_t)(b * S_ + r0) * H_ + h) * HD_ + d) = h0;
        *(__half2*)(gout + ((size_t)(b * S_ + r1) * H_ + h) * HD_ + d) = h1;
    }
}

// ---------------------------------------------------------------------------
extern "C" void kernel_launch(void* const* d_in, const int* in_sizes, int n_in,
                              void* d_out, int out_size)
{
    const float* x      = (const float*)d_in[0];
    const float* freqs  = (const float*)d_in[1];
    const float* wqkv   = (const float*)d_in[2];
    const float* wout   = (const float*)d_in[3];
    const float* ascale = (const float*)d_in[4];
    float* out = (float*)d_out;

    float* qkv;
    __half *xh, *wqh, *woh, *atth, *qh, *kh, *vh;
    cudaGetSymbolAddress((void**)&qkv,  g_qkv);
    cudaGetSymbolAddress((void**)&xh,   g_xh);
    cudaGetSymbolAddress((void**)&wqh,  g_wqh);
    cudaGetSymbolAddress((void**)&woh,  g_woh);
    cudaGetSymbolAddress((void**)&atth, g_atth);
    cudaGetSymbolAddress((void**)&qh,   g_qh);
    cudaGetSymbolAddress((void**)&kh,   g_kh);
    cudaGetSymbolAddress((void**)&vh,   g_vh);

    cudaFuncSetAttribute(gemm_fp16, cudaFuncAttributeMaxDynamicSharedMemorySize,
                         H_SMEM_BYTES);
    cudaFuncSetAttribute(flash_fp16, cudaFuncAttributeMaxDynamicSharedMemorySize,
                         F_SMEM_BYTES);

    // 0) fp16(RN) convert GEMM operands
    {
        int n4 = (M_ * D_) / 4;
        to_half<<<(n4 + 255) / 256, 256>>>((const float4*)x, (uint2*)xh, n4);
    }
    {
        int n4 = (NQKV * D_) / 4;
        to_half<<<(n4 + 255) / 256, 256>>>((const float4*)wqkv, (uint2*)wqh, n4);
    }
    {
        int n4 = (D_ * D_) / 4;
        to_half<<<(n4 + 255) / 256, 256>>>((const float4*)wout, (uint2*)woh, n4);
    }

    // 1) qkv = x @ w_qkv^T  (fp16 HMMA, fp32 accum)
    gemm_fp16<<<dim3(NQKV / 128, M_ / 128), 128, H_SMEM_BYTES>>>(xh, wqh, qkv, NQKV);

    // 2) RoPE + norm + scale -> fp16 q/k/v [b,h,s,hd]
    rope_norm_kernel<<<B_ * S_ * H_, 64>>>(qkv, freqs, ascale, qh, kh, vh);

    // 3) fp16 flash attention -> fp16 attn [b,s,h,hd]
    flash_fp16<<<dim3(S_ / 128, B_ * H_), 256, F_SMEM_BYTES>>>(qh, kh, vh, atth);

    // 4) out = attn @ w_out^T  (fp16 HMMA)
    gemm_fp16<<<dim3(D_ / 128, M_ / 128), 128, H_SMEM_BYTES>>>(atth, woh, out, D_);
}

// round 17
// speedup vs baseline: 1.8809x; 1.0403x over previous
#include <cuda_runtime.h>
#include <cuda_fp16.h>
#include <math.h>
#include <stdint.h>

// Problem constants
#define B_   2
#define S_   2048
#define D_   2048
#define H_   16
#define HD_  128
#define M_   (B_ * S_)      // 4096
#define NQKV (3 * D_)       // 6144
#define K_   D_             // 2048

// ---------------- scratch (device globals) ---------------------------------
__device__ float g_qkv[(size_t)M_ * NQKV];

__device__ __align__(1024) __half g_xh  [(size_t)M_ * D_];     // x fp16
__device__ __align__(1024) __half g_wqh [(size_t)NQKV * D_];   // w_qkv fp16
__device__ __align__(1024) __half g_woh [(size_t)D_ * D_];     // w_out fp16
__device__ __align__(1024) __half g_atth[(size_t)M_ * D_];     // attn fp16 [b,s,h,hd]
__device__ __align__(1024) __half g_qh  [(size_t)M_ * D_];     // q fp16 [b,h,s,hd]
__device__ __align__(1024) __half g_kh  [(size_t)M_ * D_];
__device__ __align__(1024) __half g_vh  [(size_t)M_ * D_];

// ======================= PTX helpers (compute_103-safe) =====================
__device__ __forceinline__ uint32_t s2u(const void* p) {
    uint32_t a;
    asm("{ .reg .u64 t; cvta.to.shared.u64 t, %1; cvt.u32.u64 %0, t; }"
        : "=r"(a) : "l"(p));
    return a;
}
__device__ __forceinline__ void cp16(uint32_t dst, const void* src) {
    asm volatile("cp.async.ca.shared.global [%0], [%1], 16;" :: "r"(dst), "l"(src));
}
__device__ __forceinline__ void cp_commit() {
    asm volatile("cp.async.commit_group;" ::: "memory");
}
__device__ __forceinline__ void cp_wait0() {
    asm volatile("cp.async.wait_group 0;" ::: "memory");
}
__device__ __forceinline__ void cp_wait1() {
    asm volatile("cp.async.wait_group 1;" ::: "memory");
}
__device__ __forceinline__ void ldsm_x4(uint32_t* r, uint32_t addr) {
    asm volatile("ldmatrix.sync.aligned.m8n8.x4.shared.b16 {%0,%1,%2,%3}, [%4];"
                 : "=r"(r[0]), "=r"(r[1]), "=r"(r[2]), "=r"(r[3]) : "r"(addr));
}
__device__ __forceinline__ void ldsm_x4t(uint32_t* r, uint32_t addr) {
    asm volatile("ldmatrix.sync.aligned.m8n8.x4.trans.shared.b16 {%0,%1,%2,%3}, [%4];"
                 : "=r"(r[0]), "=r"(r[1]), "=r"(r[2]), "=r"(r[3]) : "r"(addr));
}
__device__ __forceinline__ void mma_fp16(float* d, const uint32_t* a, const uint32_t* b) {
    asm volatile(
        "mma.sync.aligned.m16n8k16.row.col.f32.f16.f16.f32 "
        "{%0,%1,%2,%3}, {%4,%5,%6,%7}, {%8,%9}, {%0,%1,%2,%3};"
        : "+f"(d[0]), "+f"(d[1]), "+f"(d[2]), "+f"(d[3])
        : "r"(a[0]), "r"(a[1]), "r"(a[2]), "r"(a[3]), "r"(b[0]), "r"(b[1]));
}

// ======================= fp32 -> fp16(rn) convert ==========================
__global__ __launch_bounds__(256)
void to_half(const float4* __restrict__ in, uint2* __restrict__ out, int n4)
{
    int i = blockIdx.x * 256 + threadIdx.x;
    if (i >= n4) return;
    float4 v = in[i];
    __half2 h0 = __floats2half2_rn(v.x, v.y);
    __half2 h1 = __floats2half2_rn(v.z, v.w);
    uint2 r;
    r.x = *(uint32_t*)&h0;
    r.y = *(uint32_t*)&h1;
    out[i] = r;
}

// ======================= single-pass fp16 GEMM (R14, unchanged) ============
#define H_STAGE_BYTES 32768
#define H_SMEM_BYTES  (2 * H_STAGE_BYTES)   // 65536

__device__ __forceinline__ void h_load_stage(uint32_t sbase, const char* gA,
                                             const char* gB, int k0, int t)
{
    const char* gs[2] = {gA, gB};
#pragma unroll
    for (int ts = 0; ts < 2; ++ts) {
        const char* g = gs[ts] + (size_t)k0 * 2;
        uint32_t tb = sbase + ts * 16384;
#pragma unroll
        for (int i = 0; i < 8; ++i) {
            int c = t + i * 128;
            int row = c >> 3, cc = c & 7;
            uint32_t off = row * 128 + cc * 16;
            uint32_t sw = off ^ ((off >> 3) & 0x70);
            cp16(tb + sw, g + (size_t)row * (K_ * 2) + cc * 16);
        }
    }
    cp_commit();
}

__global__ __launch_bounds__(128, 2)
void gemm_fp16(const __half* __restrict__ A, const __half* __restrict__ B,
               float* __restrict__ C, int N)
{
    extern __shared__ __align__(1024) char smem_raw[];
    const int t    = threadIdx.x;
    const int wid  = t >> 5;
    const int lane = t & 31;
    const int g    = lane >> 2;
    const int c    = lane & 3;
    const int m0w  = (wid >> 1) * 64;
    const int n0w  = (wid & 1) * 64;
    const int rowBase = blockIdx.y << 7;
    const int colBase = blockIdx.x << 7;

    uint32_t sb = s2u(smem_raw);

    const int a_row = (lane & 7) + ((lane >> 3) & 1) * 8;
    const int a_cb  = (lane >> 4) * 16;
    const int b_row = (lane & 7) + ((lane >> 4) & 1) * 8;
    const int b_cb  = ((lane >> 3) & 1) * 16;
    const uint32_t xort = (uint32_t)(lane & 7) << 4;

    uint32_t abase[4], bbase[4];
#pragma unroll
    for (int mb = 0; mb < 4; ++mb)
        abase[mb] = (uint32_t)(m0w + mb * 16 + a_row) * 128 + a_cb;
#pragma unroll
    for (int nbp = 0; nbp < 4; ++nbp)
        bbase[nbp] = (uint32_t)(n0w + nbp * 16 + b_row) * 128 + b_cb;

    float acc[4][8][4];
#pragma unroll
    for (int mb = 0; mb < 4; ++mb)
#pragma unroll
        for (int nb = 0; nb < 8; ++nb)
#pragma unroll
            for (int r = 0; r < 4; ++r) acc[mb][nb][r] = 0.f;

    const char* gA = (const char*)A + (size_t)rowBase * K_ * 2;
    const char* gB = (const char*)B + (size_t)colBase * K_ * 2;

    const int NT = K_ / 64;

    h_load_stage(sb, gA, gB, 0, t);
    cp_wait0();
    __syncthreads();

    for (int kt = 0; kt < NT; ++kt) {
        const int s = kt & 1;
        if (kt + 1 < NT)
            h_load_stage(sb + (s ^ 1) * H_STAGE_BYTES, gA, gB, (kt + 1) << 6, t);
        const uint32_t stA = sb + s * H_STAGE_BYTES;
        const uint32_t stB = stA + 16384;

#pragma unroll
        for (int ks = 0; ks < 4; ++ks) {
            const uint32_t ko = (uint32_t)ks * 32;
            uint32_t a[4][4], bfr[8][2];
#pragma unroll
            for (int mb = 0; mb < 4; ++mb)
                ldsm_x4(a[mb], stA + ((abase[mb] + ko) ^ xort));
#pragma unroll
            for (int nbp = 0; nbp < 4; ++nbp) {
                uint32_t r[4];
                ldsm_x4(r, stB + ((bbase[nbp] + ko) ^ xort));
                bfr[2 * nbp][0]     = r[0];
                bfr[2 * nbp][1]     = r[1];
                bfr[2 * nbp + 1][0] = r[2];
                bfr[2 * nbp + 1][1] = r[3];
            }
#pragma unroll
            for (int mb = 0; mb < 4; ++mb)
#pragma unroll
                for (int nb = 0; nb < 8; ++nb)
                    mma_fp16(acc[mb][nb], a[mb], bfr[nb]);
        }
        if (kt + 1 < NT) cp_wait0();
        __syncthreads();
    }

#pragma unroll
    for (int mb = 0; mb < 4; ++mb)
#pragma unroll
        for (int nb = 0; nb < 8; ++nb) {
            int row = rowBase + m0w + mb * 16 + g;
            int col = colBase + n0w + nb * 8 + 2 * c;
            float2 v0 = {acc[mb][nb][0], acc[mb][nb][1]};
            float2 v1 = {acc[mb][nb][2], acc[mb][nb][3]};
            *(float2*)(C + (size_t)row * N + col)       = v0;
            *(float2*)(C + (size_t)(row + 8) * N + col) = v1;
        }
}

// ---------------------------------------------------------------------------
// RoPE + unit-norm + q*attn_scale; fp16 q/k/v in [b,h,s,hd].
// ---------------------------------------------------------------------------
__global__ __launch_bounds__(64)
void rope_norm_kernel(const float* __restrict__ qkv,
                      const float* __restrict__ freqs,
                      const float* __restrict__ scale_p,
                      __half* __restrict__ gq, __half* __restrict__ gk,
                      __half* __restrict__ gv)
{
    const int idx = blockIdx.x;
    const int h = idx % H_;
    const int s = (idx / H_) % S_;
    const int b = idx / (H_ * S_);
    const int i = threadIdx.x;

    const float* base = qkv + (size_t)(b * S_ + s) * NQKV + h * HD_;
    float q0 = base[2 * i],           q1 = base[2 * i + 1];
    float k0 = base[D_ + 2 * i],      k1 = base[D_ + 2 * i + 1];
    float v0 = base[2 * D_ + 2 * i],  v1 = base[2 * D_ + 2 * i + 1];

    float cs = freqs[((size_t)s * 64 + i) * 2 + 0];
    float sn = freqs[((size_t)s * 64 + i) * 2 + 1];

    float qr = q0 * cs - q1 * sn, qi = q0 * sn + q1 * cs;
    float kr = k0 * cs - k1 * sn, ki = k0 * sn + k1 * cs;

    float sq = qr * qr + qi * qi;
    float sk = kr * kr + ki * ki;
#pragma unroll
    for (int off = 16; off > 0; off >>= 1) {
        sq += __shfl_xor_sync(0xffffffffu, sq, off);
        sk += __shfl_xor_sync(0xffffffffu, sk, off);
    }
    __shared__ float smq[2], smk[2];
    if ((i & 31) == 0) { smq[i >> 5] = sq; smk[i >> 5] = sk; }
    __syncthreads();
    float nq = sqrtf(smq[0] + smq[1]) + 1e-6f;
    float nk = sqrtf(smk[0] + smk[1]) + 1e-6f;

    float scl = *scale_p;
    float qs = scl / nq;
    float ks = 1.0f / nk;

    size_t o = ((size_t)(b * H_ + h) * S_ + s) * HD_ + 2 * i;
    *(__half2*)(gq + o) = __floats2half2_rn(qr * qs, qi * qs);
    *(__half2*)(gk + o) = __floats2half2_rn(kr * ks, ki * ks);
    *(__half2*)(gv + o) = __floats2half2_rn(v0, v1);
}

// ---------------------------------------------------------------------------
// fp16 flash attention. BM=128, BN=128, HD=128, 256 threads.
// All tiles: 128 rows x 256B, stored as 2 panels of 128B rows, SW128 swizzle.
// smem: Q @0 (32KB), K[2] @32K (2x32KB), V @96K (32KB), P @128K (32KB) = 160KB.
// ---------------------------------------------------------------------------
#define FQ_OFF 0
#define FK_OFF 32768
#define FK_BUF 32768
#define FV_OFF 98304
#define FP_OFF 131072
#define F_PAN  16384
#define F_SMEM_BYTES 163840

// load a 128-row x 256B tile (Q/K/V) into 2-panel swizzled smem
__device__ __forceinline__ void f_load_tile(uint32_t sbase, const char* src, int t)
{
#pragma unroll
    for (int i = 0; i < 8; ++i) {
        int ci = t + i * 256;
        int row = ci >> 4, sub = ci & 15;
        uint32_t off = row * 128 + (sub & 7) * 16;
        uint32_t sw = off ^ ((off >> 3) & 0x70);
        cp16(sbase + (sub >> 3) * F_PAN + sw, src + (size_t)row * 256 + sub * 16);
    }
    cp_commit();
}

__global__ __launch_bounds__(256)
void flash_fp16(const __half* __restrict__ gq, const __half* __restrict__ gk,
                const __half* __restrict__ gv, __half* __restrict__ gout)
{
    extern __shared__ __align__(1024) char fsm[];
    uint32_t smb = s2u(fsm);
    const int t    = threadIdx.x;
    const int w    = t >> 5;
    const int lane = t & 31;
    const int g    = lane >> 2;
    const int c    = lane & 3;
    const int qt   = (gridDim.x - 1) - blockIdx.x;   // heavy tiles first
    const int bh   = blockIdx.y;
    const int b    = bh >> 4;
    const int h    = bh & 15;
    const int qr0  = w * 16;

    const char* Qg = (const char*)(gq + ((size_t)bh * S_ + qt * 128) * HD_);
    const char* Kg = (const char*)(gk + (size_t)bh * S_ * HD_);
    const char* Vg = (const char*)(gv + (size_t)bh * S_ * HD_);

    // fragment lane geometry
    const int a_row = (lane & 7) + ((lane >> 3) & 1) * 8;
    const int a_cb  = (lane >> 4) * 16;
    const int b_row = (lane & 7) + ((lane >> 4) & 1) * 8;
    const int b_cb  = ((lane >> 3) & 1) * 16;
    const uint32_t xort = (uint32_t)(lane & 7) << 4;
    const uint32_t vlbase = (uint32_t)(((lane >> 3) & 1) * 8 + (lane & 7)) * 128
                          + ((lane >> 4) & 1) * 16;

    const uint32_t aqbase = (uint32_t)(qr0 + a_row) * 128 + a_cb;   // Q/P A-frag base
    uint32_t bkbase[8];
#pragma unroll
    for (int nbp = 0; nbp < 8; ++nbp)
        bkbase[nbp] = (uint32_t)(nbp * 16 + b_row) * 128 + b_cb;    // K B-frag

    // ---- prologue: Q, K0, V0 (one group each) ----
    f_load_tile(smb + FQ_OFF, Qg, t);
    const int nkv = qt + 1;
    f_load_tile(smb + FK_OFF, Kg, t);
    f_load_tile(smb + FV_OFF, Vg, t);

    float O[16][4];
#pragma unroll
    for (int nb = 0; nb < 16; ++nb)
#pragma unroll
        for (int r = 0; r < 4; ++r) O[nb][r] = 0.f;
    float m0 = -1e30f, m1 = -1e30f, l0 = 0.f, l1 = 0.f;

    for (int kt = 0; kt < nkv; ++kt) {
        cp_wait1();              // Q + K[kt] complete (V[kt] may be in flight)
        __syncthreads();

        if (kt + 1 < nkv)        // prefetch K[kt+1]
            f_load_tile(smb + FK_OFF + ((kt + 1) & 1) * FK_BUF,
                        Kg + (size_t)(kt + 1) * 128 * 256, t);

        // ---- S = Q K^T (8 k16 steps over HD=128) ----
        const uint32_t kbuf = smb + FK_OFF + (kt & 1) * FK_BUF;
        float sacc[16][4];
#pragma unroll
        for (int nb = 0; nb < 16; ++nb)
#pragma unroll
            for (int r = 0; r < 4; ++r) sacc[nb][r] = 0.f;

#pragma unroll
        for (int ks = 0; ks < 8; ++ks) {
            const uint32_t pan = (uint32_t)(ks >> 2) * F_PAN;
            const uint32_t ko  = (uint32_t)(ks & 3) * 32;
            uint32_t a[4];
            ldsm_x4(a, smb + FQ_OFF + pan + ((aqbase + ko) ^ xort));
#pragma unroll
            for (int nbp = 0; nbp < 8; ++nbp) {
                uint32_t r[4];
                ldsm_x4(r, kbuf + pan + ((bkbase[nbp] + ko) ^ xort));
                mma_fp16(sacc[2 * nbp],     a, r);
                mma_fp16(sacc[2 * nbp + 1], a, r + 2);
            }
        }

        // ---- causal mask (diagonal tile only) ----
        if (kt == qt) {
            int rg0 = qt * 128 + qr0 + g;
#pragma unroll
            for (int nb = 0; nb < 16; ++nb) {
                int col = kt * 128 + nb * 8 + 2 * c;
                if (col     > rg0)     sacc[nb][0] = -1e30f;
                if (col + 1 > rg0)     sacc[nb][1] = -1e30f;
                if (col     > rg0 + 8) sacc[nb][2] = -1e30f;
                if (col + 1 > rg0 + 8) sacc[nb][3] = -1e30f;
            }
        }

        // ---- online softmax ----
        float rm0 = -1e30f, rm1 = -1e30f;
#pragma unroll
        for (int nb = 0; nb < 16; ++nb) {
            rm0 = fmaxf(rm0, fmaxf(sacc[nb][0], sacc[nb][1]));
            rm1 = fmaxf(rm1, fmaxf(sacc[nb][2], sacc[nb][3]));
        }
        rm0 = fmaxf(rm0, __shfl_xor_sync(0xffffffffu, rm0, 1));
        rm0 = fmaxf(rm0, __shfl_xor_sync(0xffffffffu, rm0, 2));
        rm1 = fmaxf(rm1, __shfl_xor_sync(0xffffffffu, rm1, 1));
        rm1 = fmaxf(rm1, __shfl_xor_sync(0xffffffffu, rm1, 2));
        float mn0 = fmaxf(m0, rm0), mn1 = fmaxf(m1, rm1);
        float al0 = __expf(m0 - mn0), al1 = __expf(m1 - mn1);
        float rs0 = 0.f, rs1 = 0.f;
#pragma unroll
        for (int nb = 0; nb < 16; ++nb) {
            sacc[nb][0] = __expf(sacc[nb][0] - mn0);
            sacc[nb][1] = __expf(sacc[nb][1] - mn0);
            sacc[nb][2] = __expf(sacc[nb][2] - mn1);
            sacc[nb][3] = __expf(sacc[nb][3] - mn1);
            rs0 += sacc[nb][0] + sacc[nb][1];
            rs1 += sacc[nb][2] + sacc[nb][3];
        }
        rs0 += __shfl_xor_sync(0xffffffffu, rs0, 1);
        rs0 += __shfl_xor_sync(0xffffffffu, rs0, 2);
        rs1 += __shfl_xor_sync(0xffffffffu, rs1, 1);
        rs1 += __shfl_xor_sync(0xffffffffu, rs1, 2);
        l0 = l0 * al0 + rs0;  m0 = mn0;
        l1 = l1 * al1 + rs1;  m1 = mn1;
#pragma unroll
        for (int nb = 0; nb < 16; ++nb) {
            O[nb][0] *= al0; O[nb][1] *= al0;
            O[nb][2] *= al1; O[nb][3] *= al1;
        }

        // ---- P -> smem fp16 (2 kv-panels; store XOR = g<<4) ----
        {
            const uint32_t swg = (uint32_t)g << 4;
            const uint32_t r0o = (uint32_t)(qr0 + g) * 128;
            const uint32_t r1o = r0o + 8 * 128;
#pragma unroll
            for (int nb = 0; nb < 16; ++nb) {
                uint32_t col = (uint32_t)(nb * 8 + 2 * c);
                uint32_t pan = (col >> 6) * F_PAN;
                uint32_t colb = (col & 63) * 2;
                __half2 p0 = __floats2half2_rn(sacc[nb][0], sacc[nb][1]);
                __half2 p1 = __floats2half2_rn(sacc[nb][2], sacc[nb][3]);
                *(__half2*)(fsm + FP_OFF + pan + ((r0o + colb) ^ swg)) = p0;
                *(__half2*)(fsm + FP_OFF + pan + ((r1o + colb) ^ swg)) = p1;
            }
        }
        __syncwarp();

        // ---- wait for V[kt] ----
        if (kt + 1 < nkv) cp_wait1(); else cp_wait0();
        __syncthreads();

        // ---- O += P V (8 k16 steps over BN=128; ldmatrix.trans for V) ----
#pragma unroll
        for (int kp = 0; kp < 8; ++kp) {
            const uint32_t ppan = (uint32_t)(kp >> 2) * F_PAN;  // P kv-panel
            const uint32_t pko  = (uint32_t)(kp & 3) * 32;
            const uint32_t kov  = (uint32_t)kp * 16 * 128;      // V rows
            uint32_t a[4];
            ldsm_x4(a, smb + FP_OFF + ppan + ((aqbase + pko) ^ xort));
#pragma unroll
            for (int n16 = 0; n16 < 8; ++n16) {
                const uint32_t vpan = (uint32_t)(n16 >> 2) * F_PAN;
                uint32_t off = vlbase + kov + (uint32_t)(n16 & 3) * 32;
                uint32_t r[4];
                ldsm_x4t(r, smb + FV_OFF + vpan + (off ^ xort));
                mma_fp16(O[2 * n16],     a, r);
                mma_fp16(O[2 * n16 + 1], a, r + 2);
            }
        }
        __syncthreads();   // all reads of Vs done

        if (kt + 1 < nkv)      // load V[kt+1]
            f_load_tile(smb + FV_OFF, Vg + (size_t)(kt + 1) * 128 * 256, t);
    }

    // ---- epilogue: fp16 attn ([b,s,h,hd]) ----
    float inv0 = 1.f / l0, inv1 = 1.f / l1;
    int r0 = qt * 128 + qr0 + g;
    int r1 = r0 + 8;
#pragma unroll
    for (int nb = 0; nb < 16; ++nb) {
        int d = nb * 8 + 2 * c;
        __half2 h0 = __floats2half2_rn(O[nb][0] * inv0, O[nb][1] * inv0);
        __half2 h1 = __floats2half2_rn(O[nb][2] * inv1, O[nb][3] * inv1);
        *(__half2*)(gout + ((size_t)(b * S_ + r0) * H_ + h) * HD_ + d) = h0;
        *(__half2*)(gout + ((size_t)(b * S_ + r1) * H_ + h) * HD_ + d) = h1;
    }
}

// ---------------------------------------------------------------------------
extern "C" void kernel_launch(void* const* d_in, const int* in_sizes, int n_in,
                              void* d_out, int out_size)
{
    const float* x      = (const float*)d_in[0];
    const float* freqs  = (const float*)d_in[1];
    const float* wqkv   = (const float*)d_in[2];
    const float* wout   = (const float*)d_in[3];
    const float* ascale = (const float*)d_in[4];
    float* out = (float*)d_out;

    float* qkv;
    __half *xh, *wqh, *woh, *atth, *qh, *kh, *vh;
    cudaGetSymbolAddress((void**)&qkv,  g_qkv);
    cudaGetSymbolAddress((void**)&xh,   g_xh);
    cudaGetSymbolAddress((void**)&wqh,  g_wqh);
    cudaGetSymbolAddress((void**)&woh,  g_woh);
    cudaGetSymbolAddress((void**)&atth, g_atth);
    cudaGetSymbolAddress((void**)&qh,   g_qh);
    cudaGetSymbolAddress((void**)&kh,   g_kh);
    cudaGetSymbolAddress((void**)&vh,   g_vh);

    cudaFuncSetAttribute(gemm_fp16, cudaFuncAttributeMaxDynamicSharedMemorySize,
                         H_SMEM_BYTES);
    cudaFuncSetAttribute(flash_fp16, cudaFuncAttributeMaxDynamicSharedMemorySize,
                         F_SMEM_BYTES);

    // 0) fp16(RN) convert GEMM operands
    {
        int n4 = (M_ * D_) / 4;
        to_half<<<(n4 + 255) / 256, 256>>>((const float4*)x, (uint2*)xh, n4);
    }
    {
        int n4 = (NQKV * D_) / 4;
        to_half<<<(n4 + 255) / 256, 256>>>((const float4*)wqkv, (uint2*)wqh, n4);
    }
    {
        int n4 = (D_ * D_) / 4;
        to_half<<<(n4 + 255) / 256, 256>>>((const float4*)wout, (uint2*)woh, n4);
    }

    // 1) qkv = x @ w_qkv^T  (fp16 HMMA, fp32 accum)
    gemm_fp16<<<dim3(NQKV / 128, M_ / 128), 128, H_SMEM_BYTES>>>(xh, wqh, qkv, NQKV);

    // 2) RoPE + norm + scale -> fp16 q/k/v [b,h,s,hd]
    rope_norm_kernel<<<B_ * S_ * H_, 64>>>(qkv, freqs, ascale, qh, kh, vh);

    // 3) fp16 flash attention (BM=BN=128) -> fp16 attn [b,s,h,hd]
    flash_fp16<<<dim3(S_ / 128, B_ * H_), 256, F_SMEM_BYTES>>>(qh, kh, vh, atth);

    // 4) out = attn @ w_out^T  (fp16 HMMA)
    gemm_fp16<<<dim3(D_ / 128, M_ / 128), 128, H_SMEM_BYTES>>>(atth, woh, out, D_);
}